// round 5
// baseline (speedup 1.0000x reference)
#include <cuda_runtime.h>
#include <cuda_fp16.h>
#include <math.h>

#define VSZ 5000
#define HSZ 1024
#define ESZ 512
#define BSZ 64
#define TSZ 256
#define H4  (4 * HSZ)
#define MROWS (BSZ * TSZ)   // 16384
#define NBLK 128

// ---------------- scratch ---------------------------------------------------
__device__ float g_x [(size_t)MROWS * ESZ];
__device__ float g_xg[(size_t)MROWS * H4];
__device__ float g_h1[(size_t)MROWS * HSZ];
__device__ float g_h2[(size_t)MROWS * HSZ];
__device__ unsigned g_hfragH[2][BSZ * HSZ / 2];  // fp16-packed A fragments (128KB/buf)
__device__ unsigned g_ctr[2 * TSZ];

// ---------------- helpers ---------------------------------------------------
__device__ __forceinline__ unsigned pack2(float x, float y) {
    __half2 h = __floats2half2_rn(x, y);
    return *(unsigned*)&h;
}
__device__ __forceinline__ void mma16(float* c, const unsigned* a, const unsigned* b) {
    asm volatile(
        "mma.sync.aligned.m16n8k16.row.col.f32.f16.f16.f32 "
        "{%0,%1,%2,%3}, {%4,%5,%6,%7}, {%8,%9}, {%0,%1,%2,%3};\n"
        : "+f"(c[0]), "+f"(c[1]), "+f"(c[2]), "+f"(c[3])
        : "r"(a[0]), "r"(a[1]), "r"(a[2]), "r"(a[3]), "r"(b[0]), "r"(b[1]));
}

// ---------------- misc small kernels ----------------------------------------
__global__ void zero_ctr_kernel() { g_ctr[threadIdx.x] = 0u; }

__global__ void embed_kernel(const int* __restrict__ input,
                             const float* __restrict__ embed_W)
{
    int row = blockIdx.x;
    int idx = input[row];
    const float4* src = (const float4*)(embed_W + (size_t)idx * ESZ);
    float4* dst = (float4*)(g_x + (size_t)row * ESZ);
    dst[threadIdx.x] = src[threadIdx.x];
}

// ---------------- fp16 tensor GEMM: C = A(MxK) @ W(NxK)^T + b0 (+ b1) ------
// BM=128, BN=64, BK=16, 256 threads (8 warps as 4m x 2n, warp tile 32x32)
// SMEM tiles hold half2 k-pairs: As[row][8 pairs] padded to 12.
__global__ void __launch_bounds__(256, 2)
tgemm(const float* __restrict__ A, const float* __restrict__ W,
      const float* __restrict__ b0v, const float* __restrict__ b1v,
      float* __restrict__ C, int M, int N, int K)
{
    __shared__ unsigned As[2][128][12];
    __shared__ unsigned Ws[2][64][12];

    const int tid = threadIdx.x, lane = tid & 31, wid = tid >> 5;
    const int m0 = blockIdx.y * 128, n0 = blockIdx.x * 64;
    const int wm = (wid >> 1) * 32, wn = (wid & 1) * 32;
    const int r = lane >> 2, q = lane & 3;

    float acc[2][4][4];
    #pragma unroll
    for (int i = 0; i < 2; i++)
        #pragma unroll
        for (int j = 0; j < 4; j++)
            #pragma unroll
            for (int k = 0; k < 4; k++) acc[i][j][k] = 0.f;

    const int NIT = K / 16;

    float4 aR[2]; float4 bR;
    const int arow0 = tid >> 2;
    const int akg   = (tid & 3) * 4;      // float offset
    const int ap0   = (tid & 3) * 2;      // pair offset
    const int bnl   = tid >> 2;
    const int wrow  = n0 + bnl;
    const bool wok  = (wrow < N);

    {
        aR[0] = *(const float4*)&A[(size_t)(m0 + arow0) * K + akg];
        aR[1] = *(const float4*)&A[(size_t)(m0 + 64 + arow0) * K + akg];
        bR = wok ? *(const float4*)&W[(size_t)wrow * K + akg] : make_float4(0,0,0,0);
        As[0][arow0][ap0]        = pack2(aR[0].x, aR[0].y);
        As[0][arow0][ap0 + 1]    = pack2(aR[0].z, aR[0].w);
        As[0][64+arow0][ap0]     = pack2(aR[1].x, aR[1].y);
        As[0][64+arow0][ap0 + 1] = pack2(aR[1].z, aR[1].w);
        Ws[0][bnl][ap0]          = pack2(bR.x, bR.y);
        Ws[0][bnl][ap0 + 1]      = pack2(bR.z, bR.w);
    }
    __syncthreads();

    for (int it = 0; it < NIT; ++it) {
        if (it + 1 < NIT) {
            int k0 = (it + 1) * 16;
            aR[0] = *(const float4*)&A[(size_t)(m0 + arow0) * K + k0 + akg];
            aR[1] = *(const float4*)&A[(size_t)(m0 + 64 + arow0) * K + k0 + akg];
            bR = wok ? *(const float4*)&W[(size_t)wrow * K + k0 + akg] : make_float4(0,0,0,0);
        }
        const int bf = it & 1;
        {
            unsigned af[2][4];
            #pragma unroll
            for (int tm = 0; tm < 2; tm++) {
                af[tm][0] = As[bf][wm + tm*16 + r    ][q];
                af[tm][1] = As[bf][wm + tm*16 + r + 8][q];
                af[tm][2] = As[bf][wm + tm*16 + r    ][q + 4];
                af[tm][3] = As[bf][wm + tm*16 + r + 8][q + 4];
            }
            #pragma unroll
            for (int tn = 0; tn < 4; tn++) {
                unsigned bg[2];
                bg[0] = Ws[bf][wn + tn*8 + r][q];
                bg[1] = Ws[bf][wn + tn*8 + r][q + 4];
                #pragma unroll
                for (int tm = 0; tm < 2; tm++)
                    mma16(acc[tm][tn], af[tm], bg);
            }
        }
        if (it + 1 < NIT) {
            const int nb = (it + 1) & 1;
            As[nb][arow0][ap0]        = pack2(aR[0].x, aR[0].y);
            As[nb][arow0][ap0 + 1]    = pack2(aR[0].z, aR[0].w);
            As[nb][64+arow0][ap0]     = pack2(aR[1].x, aR[1].y);
            As[nb][64+arow0][ap0 + 1] = pack2(aR[1].z, aR[1].w);
            Ws[nb][bnl][ap0]          = pack2(bR.x, bR.y);
            Ws[nb][bnl][ap0 + 1]      = pack2(bR.z, bR.w);
        }
        __syncthreads();
    }

    #pragma unroll
    for (int tm = 0; tm < 2; tm++) {
        #pragma unroll
        for (int tn = 0; tn < 4; tn++) {
            int n = n0 + wn + tn*8 + 2*q;
            float bb0 = 0.f, bb1 = 0.f;
            if (n < N)     bb0 = b0v[n]     + (b1v ? b1v[n]     : 0.f);
            if (n + 1 < N) bb1 = b0v[n + 1] + (b1v ? b1v[n + 1] : 0.f);
            int m = m0 + wm + tm*16 + r;
            if (n < N) {
                C[(size_t)m * N + n]       = acc[tm][tn][0] + bb0;
                C[(size_t)(m+8) * N + n]   = acc[tm][tn][2] + bb0;
            }
            if (n + 1 < N) {
                C[(size_t)m * N + n + 1]     = acc[tm][tn][1] + bb1;
                C[(size_t)(m+8) * N + n + 1] = acc[tm][tn][3] + bb1;
            }
        }
    }
}

// ---------------- persistent LSTM layer, fp16 -------------------------------
// 128 blocks x 256 thr. Block owns 32 gate cols (8 h-units x 4 gates).
// W as fp16 m16n8k16 B-fragments in SMEM (64KB, once). A fragments fp16-packed
// in global (L2-resident broadcast, __ldcg), no syncthreads in K-loop.
__global__ void __launch_bounds__(256, 1)
lstm_persist3(const float* __restrict__ Xg, const float* __restrict__ Whh,
              float* __restrict__ h_all, unsigned* __restrict__ ctr)
{
    extern __shared__ unsigned smu[];
    unsigned* Wp = smu;                  // [4tn][64c][32lane][2] = 16384 words
    float*    Gb = (float*)(smu + 16384);// [2kh][64][33]

    const int tid = threadIdx.x, lane = tid & 31, wid = tid >> 5;
    const int h0 = blockIdx.x * 8;
    const int mw = wid & 3, kh = wid >> 2;
    const int r = lane >> 2, q = lane & 3;

    // ---- pack W slice into SMEM fp16 B-fragments (once) ----
    for (int idx = tid; idx < 32 * 512; idx += 256) {
        int nl = idx >> 9;          // 0..31 local gate col
        int kp = idx & 511;         // k pair
        int k  = kp * 2;
        int wrow = ((nl >> 3) * HSZ) + h0 + (nl & 7);
        float2 v = *(const float2*)&Whh[(size_t)wrow * HSZ + k];
        int tn = nl >> 3, rr = nl & 7;
        int c = k >> 4, kk = k & 15;
        int f = (kk >= 8) ? 1 : 0;
        int qq = (kk & 7) >> 1;
        Wp[((tn*64 + c)*32 + rr*4 + qq)*2 + f] = pack2(v.x, v.y);
    }
    __syncthreads();

    // epilogue / producer mapping (constant over t)
    const int bb0i = tid >> 3, jj = tid & 7;
    const int khid = h0 + jj;
    int pk[2]; size_t ha[2];
    #pragma unroll
    for (int half = 0; half < 2; half++) {
        int b = bb0i + 32 * half;
        int g = b >> 4, ml = b & 15;
        int c = khid >> 4, kk = khid & 15;
        int e = ((ml >= 8) ? 1 : 0) + ((kk >= 8) ? 2 : 0);
        int lp = (ml & 7) * 4 + ((kk & 7) >> 1);
        pk[half] = ((((g*64 + c)*32 + lp)*4 + e) << 1) + (kk & 1);  // half index
        ha[half] = ((size_t)b * TSZ) * HSZ + h0 + jj;
    }

    float cr0 = 0.f, cr1 = 0.f;
    volatile unsigned* vctr = ctr;

    for (int t = 0; t < TSZ; t++) {
        // prefetch Xg for this step
        float xv[2][4];
        #pragma unroll
        for (int half = 0; half < 2; half++) {
            size_t xb = ((size_t)(bb0i + 32 * half) * TSZ + t) * H4 + h0 + jj;
            #pragma unroll
            for (int g4 = 0; g4 < 4; g4++) xv[half][g4] = Xg[xb + g4 * HSZ];
        }

        float acc[4][4];
        #pragma unroll
        for (int i = 0; i < 4; i++)
            #pragma unroll
            for (int j = 0; j < 4; j++) acc[i][j] = 0.f;

        if (t > 0) {
            if (tid == 0) { while (vctr[t - 1] < NBLK) { } }
            __syncthreads();
            __threadfence();

            const uint4* ab = (const uint4*)g_hfragH[(t - 1) & 1]
                              + (mw*64 + kh*32) * 32 + lane;
            const unsigned* wb = Wp + (kh*32)*64 + lane*2;

            #pragma unroll 4
            for (int c = 0; c < 32; c++) {
                uint4 a4 = __ldcg(ab + c*32);
                unsigned af[4] = { a4.x, a4.y, a4.z, a4.w };
                #pragma unroll
                for (int tn = 0; tn < 4; tn++) {
                    const unsigned* wp2 = wb + (tn*64 + c)*64;
                    unsigned bg[2] = { wp2[0], wp2[1] };
                    mma16(acc[tn], af, bg);
                }
            }
        }

        // stage accumulators (per k-half) to SMEM
        #pragma unroll
        for (int tn = 0; tn < 4; tn++) {
            int col = tn * 8 + 2 * q;
            float* gb = &Gb[kh * 64 * 33];
            gb[(mw*16 + r    )*33 + col]     = acc[tn][0];
            gb[(mw*16 + r    )*33 + col + 1] = acc[tn][1];
            gb[(mw*16 + r + 8)*33 + col]     = acc[tn][2];
            gb[(mw*16 + r + 8)*33 + col + 1] = acc[tn][3];
        }
        __syncthreads();

        // cell update (c in registers), dual h write (fp32 + fp16 fragment)
        __half* hfo = (__half*)g_hfragH[t & 1];
        #pragma unroll
        for (int half = 0; half < 2; half++) {
            int b = bb0i + 32 * half;
            float iv = Gb[b*33 + jj]      + Gb[(64+b)*33 + jj]      + xv[half][0];
            float fv = Gb[b*33 + 8 + jj]  + Gb[(64+b)*33 + 8 + jj]  + xv[half][1];
            float gv = Gb[b*33 + 16 + jj] + Gb[(64+b)*33 + 16 + jj] + xv[half][2];
            float ov = Gb[b*33 + 24 + jj] + Gb[(64+b)*33 + 24 + jj] + xv[half][3];
            float cp = half ? cr1 : cr0;
            float si = 1.f / (1.f + expf(-iv));
            float sf = 1.f / (1.f + expf(-fv));
            float so = 1.f / (1.f + expf(-ov));
            float cn = sf * cp + si * tanhf(gv);
            float hn = so * tanhf(cn);
            if (half) cr1 = cn; else cr0 = cn;
            h_all[ha[half] + (size_t)t * HSZ] = hn;
            hfo[pk[half]] = __float2half_rn(hn);
        }

        __threadfence();
        __syncthreads();
        if (tid == 0) atomicAdd(&ctr[t], 1u);
    }
}

// ---------------- launch ----------------------------------------------------
#define SMEM_P3 (16384 * 4 + 2 * 64 * 33 * 4)

extern "C" void kernel_launch(void* const* d_in, const int* in_sizes, int n_in,
                              void* d_out, int out_size)
{
    const int*   input  = (const int*)  d_in[0];
    const float* embedW = (const float*)d_in[2];
    const float* W_ih1  = (const float*)d_in[3];
    const float* W_hh1  = (const float*)d_in[4];
    const float* b_ih1  = (const float*)d_in[5];
    const float* b_hh1  = (const float*)d_in[6];
    const float* W_ih2  = (const float*)d_in[7];
    const float* W_hh2  = (const float*)d_in[8];
    const float* b_ih2  = (const float*)d_in[9];
    const float* b_hh2  = (const float*)d_in[10];
    const float* lin_W  = (const float*)d_in[11];
    const float* lin_b  = (const float*)d_in[12];
    float* out = (float*)d_out;

    float *x, *xg, *h1, *h2; unsigned* ctr;
    cudaGetSymbolAddress((void**)&x,   g_x);
    cudaGetSymbolAddress((void**)&xg,  g_xg);
    cudaGetSymbolAddress((void**)&h1,  g_h1);
    cudaGetSymbolAddress((void**)&h2,  g_h2);
    cudaGetSymbolAddress((void**)&ctr, g_ctr);

    cudaFuncSetAttribute(lstm_persist3,
                         cudaFuncAttributeMaxDynamicSharedMemorySize, SMEM_P3);

    zero_ctr_kernel<<<1, 2 * TSZ>>>();
    embed_kernel<<<MROWS, 128>>>(input, embedW);

    {   // Xg1 = x @ W_ih1^T + b_ih1 + b_hh1
        dim3 grid(H4 / 64, MROWS / 128);
        tgemm<<<grid, 256>>>(x, W_ih1, b_ih1, b_hh1, xg, MROWS, H4, ESZ);
    }
    lstm_persist3<<<NBLK, 256, SMEM_P3>>>(xg, W_hh1, h1, ctr);

    {   // Xg2 = h1 @ W_ih2^T + b_ih2 + b_hh2
        dim3 grid(H4 / 64, MROWS / 128);
        tgemm<<<grid, 256>>>(h1, W_ih2, b_ih2, b_hh2, xg, MROWS, H4, HSZ);
    }
    lstm_persist3<<<NBLK, 256, SMEM_P3>>>(xg, W_hh2, h2, ctr + TSZ);

    {   // outs = h2 @ lin_W^T + lin_b
        dim3 grid((VSZ + 63) / 64, MROWS / 128);
        tgemm<<<grid, 256>>>(h2, lin_W, lin_b, nullptr, out, MROWS, VSZ, HSZ);
    }
}

// round 6
// speedup vs baseline: 1.2916x; 1.2916x over previous
#include <cuda_runtime.h>
#include <cuda_fp16.h>
#include <math.h>

#define VSZ 5000
#define HSZ 1024
#define ESZ 512
#define BSZ 64
#define TSZ 256
#define H4  (4 * HSZ)
#define MROWS (BSZ * TSZ)   // 16384
#define NBLK 128
#define KP 20               // tgemm padded k-stride

// ---------------- scratch ---------------------------------------------------
__device__ float g_x [(size_t)MROWS * ESZ];
__device__ float g_xg[(size_t)MROWS * H4];
__device__ float g_h1[(size_t)MROWS * HSZ];
__device__ float g_h2[(size_t)MROWS * HSZ];
__device__ unsigned g_hfragH[2][BSZ * HSZ / 2];  // fp16 A fragments, 2 buffers
__device__ unsigned g_ctr[2 * TSZ];

// ---------------- helpers ---------------------------------------------------
__device__ __forceinline__ unsigned f2tf(float x) {
    unsigned u; asm("cvt.rna.tf32.f32 %0, %1;" : "=r"(u) : "f"(x)); return u;
}
__device__ __forceinline__ unsigned pack2(float x, float y) {
    __half2 h = __floats2half2_rn(x, y);
    return *(unsigned*)&h;
}
__device__ __forceinline__ void mma8(float* c, const unsigned* a, const unsigned* b) {
    asm volatile(
        "mma.sync.aligned.m16n8k8.row.col.f32.tf32.tf32.f32 "
        "{%0,%1,%2,%3}, {%4,%5,%6,%7}, {%8,%9}, {%0,%1,%2,%3};\n"
        : "+f"(c[0]), "+f"(c[1]), "+f"(c[2]), "+f"(c[3])
        : "r"(a[0]), "r"(a[1]), "r"(a[2]), "r"(a[3]), "r"(b[0]), "r"(b[1]));
}
__device__ __forceinline__ void mma16(float* c, const unsigned* a, const unsigned* b) {
    asm volatile(
        "mma.sync.aligned.m16n8k16.row.col.f32.f16.f16.f32 "
        "{%0,%1,%2,%3}, {%4,%5,%6,%7}, {%8,%9}, {%0,%1,%2,%3};\n"
        : "+f"(c[0]), "+f"(c[1]), "+f"(c[2]), "+f"(c[3])
        : "r"(a[0]), "r"(a[1]), "r"(a[2]), "r"(a[3]), "r"(b[0]), "r"(b[1]));
}
__device__ __forceinline__ void red_release(unsigned* p) {
    asm volatile("red.release.gpu.global.add.u32 [%0], 1;" :: "l"(p) : "memory");
}
__device__ __forceinline__ unsigned ld_acquire(const unsigned* p) {
    unsigned v;
    asm volatile("ld.acquire.gpu.global.b32 %0, [%1];" : "=r"(v) : "l"(p) : "memory");
    return v;
}

// ---------------- misc small kernels ----------------------------------------
__global__ void zero_ctr_kernel() { g_ctr[threadIdx.x] = 0u; }

__global__ void embed_kernel(const int* __restrict__ input,
                             const float* __restrict__ embed_W)
{
    int row = blockIdx.x;
    int idx = input[row];
    const float4* src = (const float4*)(embed_W + (size_t)idx * ESZ);
    float4* dst = (float4*)(g_x + (size_t)row * ESZ);
    dst[threadIdx.x] = src[threadIdx.x];
}

// ---------------- tf32 tensor GEMM (r4 version, known good) -----------------
__global__ void __launch_bounds__(256, 2)
tgemm(const float* __restrict__ A, const float* __restrict__ W,
      const float* __restrict__ b0v, const float* __restrict__ b1v,
      float* __restrict__ C, int M, int N, int K)
{
    __shared__ unsigned As[2][128][KP];
    __shared__ unsigned Ws[2][64][KP];

    const int tid = threadIdx.x, lane = tid & 31, wid = tid >> 5;
    const int m0 = blockIdx.y * 128, n0 = blockIdx.x * 64;
    const int wm = (wid >> 1) * 32, wn = (wid & 1) * 32;
    const int r = lane >> 2, q = lane & 3;

    float acc[2][4][4];
    #pragma unroll
    for (int i = 0; i < 2; i++)
        #pragma unroll
        for (int j = 0; j < 4; j++)
            #pragma unroll
            for (int k = 0; k < 4; k++) acc[i][j][k] = 0.f;

    const int NIT = K / 16;

    float4 aR[2]; float4 bR;
    const int arow0 = tid >> 2;
    const int akg   = (tid & 3) * 4;
    const int bnl   = tid >> 2;
    const int wrow  = n0 + bnl;
    const bool wok  = (wrow < N);

    {
        aR[0] = *(const float4*)&A[(size_t)(m0 + arow0) * K + akg];
        aR[1] = *(const float4*)&A[(size_t)(m0 + 64 + arow0) * K + akg];
        bR = wok ? *(const float4*)&W[(size_t)wrow * K + akg] : make_float4(0,0,0,0);
        unsigned* s0 = &As[0][arow0][akg];
        s0[0]=f2tf(aR[0].x); s0[1]=f2tf(aR[0].y); s0[2]=f2tf(aR[0].z); s0[3]=f2tf(aR[0].w);
        unsigned* s1 = &As[0][64 + arow0][akg];
        s1[0]=f2tf(aR[1].x); s1[1]=f2tf(aR[1].y); s1[2]=f2tf(aR[1].z); s1[3]=f2tf(aR[1].w);
        unsigned* sw = &Ws[0][bnl][akg];
        sw[0]=f2tf(bR.x); sw[1]=f2tf(bR.y); sw[2]=f2tf(bR.z); sw[3]=f2tf(bR.w);
    }
    __syncthreads();

    for (int it = 0; it < NIT; ++it) {
        if (it + 1 < NIT) {
            int k0 = (it + 1) * 16;
            aR[0] = *(const float4*)&A[(size_t)(m0 + arow0) * K + k0 + akg];
            aR[1] = *(const float4*)&A[(size_t)(m0 + 64 + arow0) * K + k0 + akg];
            bR = wok ? *(const float4*)&W[(size_t)wrow * K + k0 + akg] : make_float4(0,0,0,0);
        }
        const int bf = it & 1;
        #pragma unroll
        for (int kc = 0; kc < 16; kc += 8) {
            unsigned af[2][4];
            #pragma unroll
            for (int tm = 0; tm < 2; tm++) {
                af[tm][0] = As[bf][wm + tm*16 + r    ][kc + q];
                af[tm][1] = As[bf][wm + tm*16 + r + 8][kc + q];
                af[tm][2] = As[bf][wm + tm*16 + r    ][kc + q + 4];
                af[tm][3] = As[bf][wm + tm*16 + r + 8][kc + q + 4];
            }
            unsigned bg[4][2];
            #pragma unroll
            for (int tn = 0; tn < 4; tn++) {
                bg[tn][0] = Ws[bf][wn + tn*8 + r][kc + q];
                bg[tn][1] = Ws[bf][wn + tn*8 + r][kc + q + 4];
            }
            #pragma unroll
            for (int tm = 0; tm < 2; tm++)
                #pragma unroll
                for (int tn = 0; tn < 4; tn++)
                    mma8(acc[tm][tn], af[tm], bg[tn]);
        }
        if (it + 1 < NIT) {
            const int nb = (it + 1) & 1;
            unsigned* s0 = &As[nb][arow0][akg];
            s0[0]=f2tf(aR[0].x); s0[1]=f2tf(aR[0].y); s0[2]=f2tf(aR[0].z); s0[3]=f2tf(aR[0].w);
            unsigned* s1 = &As[nb][64 + arow0][akg];
            s1[0]=f2tf(aR[1].x); s1[1]=f2tf(aR[1].y); s1[2]=f2tf(aR[1].z); s1[3]=f2tf(aR[1].w);
            unsigned* sw = &Ws[nb][bnl][akg];
            sw[0]=f2tf(bR.x); sw[1]=f2tf(bR.y); sw[2]=f2tf(bR.z); sw[3]=f2tf(bR.w);
        }
        __syncthreads();
    }

    #pragma unroll
    for (int tm = 0; tm < 2; tm++) {
        #pragma unroll
        for (int tn = 0; tn < 4; tn++) {
            int n = n0 + wn + tn*8 + 2*q;
            float bb0 = 0.f, bb1 = 0.f;
            if (n < N)     bb0 = b0v[n]     + (b1v ? b1v[n]     : 0.f);
            if (n + 1 < N) bb1 = b0v[n + 1] + (b1v ? b1v[n + 1] : 0.f);
            int m = m0 + wm + tm*16 + r;
            if (n < N) {
                C[(size_t)m * N + n]       = acc[tm][tn][0] + bb0;
                C[(size_t)(m+8) * N + n]   = acc[tm][tn][2] + bb0;
            }
            if (n + 1 < N) {
                C[(size_t)m * N + n + 1]     = acc[tm][tn][1] + bb1;
                C[(size_t)(m+8) * N + n + 1] = acc[tm][tn][3] + bb1;
            }
        }
    }
}

// ---------------- persistent LSTM layer, v4 ---------------------------------
// Grid 128 = 2 m-blocks x 64 n-blocks. Block: 32 batch rows x 64 gate cols
// (= 16 h-units x 4 gates). W slice as fp16 B-fragments in SMEM (128KB, once).
// A fragments fp16 in global (__ldcg, 64KB/block/step). 8 warps = 2m x 2n x 2k.
__global__ void __launch_bounds__(256, 1)
lstm_persist4(const float* __restrict__ Xg, const float* __restrict__ Whh,
              float* __restrict__ h_all, unsigned* __restrict__ ctr)
{
    extern __shared__ unsigned smu[];
    unsigned* Wp = smu;                   // [8tn][64c][32lane][2] = 32768 words
    float*    Gb = (float*)(smu + 32768); // [2kh][32][68]

    const int tid = threadIdx.x, lane = tid & 31, wid = tid >> 5;
    const int bm = blockIdx.x >> 6;       // 0..1 (batch half)
    const int bn = blockIdx.x & 63;       // 0..63 (16 h-units)
    const int h0 = bn * 16;
    const int mw = wid & 1, nw = (wid >> 1) & 1, kh = wid >> 2;
    const int r = lane >> 2, q = lane & 3;

    // ---- pack W slice (64 gate cols x 1024 k) into SMEM fp16 B-frags ----
    for (int idx = tid; idx < 64 * 512; idx += 256) {
        int nl = idx >> 9;            // 0..63: gate*16 + hunit
        int k  = (idx & 511) * 2;
        int wrow = ((nl >> 4) * HSZ) + h0 + (nl & 15);
        float2 v = *(const float2*)&Whh[(size_t)wrow * HSZ + k];
        int tn = nl >> 3, rr = nl & 7;
        int c = k >> 4, kk = k & 15;
        int f = (kk >= 8) ? 1 : 0;
        int qq = (kk & 7) >> 1;
        Wp[((tn*64 + c)*32 + rr*4 + qq)*2 + f] = pack2(v.x, v.y);
    }
    __syncthreads();

    // epilogue mapping: thread -> (j, brow); handles local rows brow, brow+16
    const int jb = tid & 15, brow = tid >> 4;   // j 0..15, brow 0..15
    const int hcol = h0 + jb;
    int pk[2]; size_t ha[2];
    #pragma unroll
    for (int half = 0; half < 2; half++) {
        int B = bm*32 + brow + 16*half;         // global batch row
        int g = B >> 4, ml = B & 15;
        int c = hcol >> 4, kk = hcol & 15;      // c == bn, kk == jb
        int e = ((ml >= 8) ? 1 : 0) + ((kk >= 8) ? 2 : 0);
        int lp = (ml & 7) * 4 + ((kk & 7) >> 1);
        pk[half] = ((((g*64 + c)*32 + lp)*4 + e) << 1) + (kk & 1);
        ha[half] = ((size_t)B * TSZ) * HSZ + hcol;
    }

    // consumer A-fragment base: m-tile = bm*2 + mw, k-half offset kh*32
    const uint4* abase0 = (const uint4*)g_hfragH[0] + (((bm*2 + mw)*64 + kh*32)*32 + lane);
    const uint4* abase1 = (const uint4*)g_hfragH[1] + (((bm*2 + mw)*64 + kh*32)*32 + lane);

    float cr0 = 0.f, cr1 = 0.f;

    for (int t = 0; t < TSZ; t++) {
        // prefetch Xg for this step (before barrier wait)
        float xv[2][4];
        #pragma unroll
        for (int half = 0; half < 2; half++) {
            size_t xb = ((size_t)(bm*32 + brow + 16*half) * TSZ + t) * H4 + hcol;
            #pragma unroll
            for (int g4 = 0; g4 < 4; g4++) xv[half][g4] = Xg[xb + g4 * HSZ];
        }

        float acc[4][4];
        #pragma unroll
        for (int i = 0; i < 4; i++)
            #pragma unroll
            for (int j = 0; j < 4; j++) acc[i][j] = 0.f;

        if (t > 0) {
            if (tid == 0) { while (ld_acquire(&ctr[t - 1]) < NBLK) { } }
            __syncthreads();

            const uint4* ab = ((t - 1) & 1) ? abase1 : abase0;
            const unsigned* wb = Wp + (nw*4*64 + kh*32)*64 + lane*2;

            #pragma unroll 8
            for (int cc = 0; cc < 32; cc++) {
                uint4 a4 = __ldcg(ab + cc*32);
                unsigned af[4] = { a4.x, a4.y, a4.z, a4.w };
                #pragma unroll
                for (int tn = 0; tn < 4; tn++) {
                    const unsigned* wp2 = wb + (tn*64 + cc)*64;
                    unsigned bg[2] = { wp2[0], wp2[1] };
                    mma16(acc[tn], af, bg);
                }
            }
        }

        // stage accumulators to SMEM: rows mw*16.., cols nw*32 + tn*8 + 2q
        #pragma unroll
        for (int tn = 0; tn < 4; tn++) {
            int col = nw*32 + tn*8 + 2*q;
            float* gb = &Gb[kh * 32 * 68];
            gb[(mw*16 + r    )*68 + col]     = acc[tn][0];
            gb[(mw*16 + r    )*68 + col + 1] = acc[tn][1];
            gb[(mw*16 + r + 8)*68 + col]     = acc[tn][2];
            gb[(mw*16 + r + 8)*68 + col + 1] = acc[tn][3];
        }
        __syncthreads();

        // cell update: thread handles (brow, jb) and (brow+16, jb)
        __half* hfo = (__half*)g_hfragH[t & 1];
        #pragma unroll
        for (int half = 0; half < 2; half++) {
            int b = brow + 16*half;     // local row
            float iv = Gb[b*68 + 0*16 + jb] + Gb[32*68 + b*68 + 0*16 + jb] + xv[half][0];
            float fv = Gb[b*68 + 1*16 + jb] + Gb[32*68 + b*68 + 1*16 + jb] + xv[half][1];
            float gv = Gb[b*68 + 2*16 + jb] + Gb[32*68 + b*68 + 2*16 + jb] + xv[half][2];
            float ov = Gb[b*68 + 3*16 + jb] + Gb[32*68 + b*68 + 3*16 + jb] + xv[half][3];
            float cp = half ? cr1 : cr0;
            float si = 1.f / (1.f + expf(-iv));
            float sf = 1.f / (1.f + expf(-fv));
            float so = 1.f / (1.f + expf(-ov));
            float cn = sf * cp + si * tanhf(gv);
            float hn = so * tanhf(cn);
            if (half) cr1 = cn; else cr0 = cn;
            h_all[ha[half] + (size_t)t * HSZ] = hn;
            hfo[pk[half]] = __float2half_rn(hn);
        }

        __syncthreads();
        if (tid == 0) red_release(&ctr[t]);
    }
}

// ---------------- launch ----------------------------------------------------
#define SMEM_P4 (32768 * 4 + 2 * 32 * 68 * 4)

extern "C" void kernel_launch(void* const* d_in, const int* in_sizes, int n_in,
                              void* d_out, int out_size)
{
    const int*   input  = (const int*)  d_in[0];
    const float* embedW = (const float*)d_in[2];
    const float* W_ih1  = (const float*)d_in[3];
    const float* W_hh1  = (const float*)d_in[4];
    const float* b_ih1  = (const float*)d_in[5];
    const float* b_hh1  = (const float*)d_in[6];
    const float* W_ih2  = (const float*)d_in[7];
    const float* W_hh2  = (const float*)d_in[8];
    const float* b_ih2  = (const float*)d_in[9];
    const float* b_hh2  = (const float*)d_in[10];
    const float* lin_W  = (const float*)d_in[11];
    const float* lin_b  = (const float*)d_in[12];
    float* out = (float*)d_out;

    float *x, *xg, *h1, *h2; unsigned* ctr;
    cudaGetSymbolAddress((void**)&x,   g_x);
    cudaGetSymbolAddress((void**)&xg,  g_xg);
    cudaGetSymbolAddress((void**)&h1,  g_h1);
    cudaGetSymbolAddress((void**)&h2,  g_h2);
    cudaGetSymbolAddress((void**)&ctr, g_ctr);

    cudaFuncSetAttribute(lstm_persist4,
                         cudaFuncAttributeMaxDynamicSharedMemorySize, SMEM_P4);

    zero_ctr_kernel<<<1, 2 * TSZ>>>();
    embed_kernel<<<MROWS, 128>>>(input, embedW);

    {   // Xg1 = x @ W_ih1^T + b_ih1 + b_hh1
        dim3 grid(H4 / 64, MROWS / 128);
        tgemm<<<grid, 256>>>(x, W_ih1, b_ih1, b_hh1, xg, MROWS, H4, ESZ);
    }
    lstm_persist4<<<NBLK, 256, SMEM_P4>>>(xg, W_hh1, h1, ctr);

    {   // Xg2 = h1 @ W_ih2^T + b_ih2 + b_hh2
        dim3 grid(H4 / 64, MROWS / 128);
        tgemm<<<grid, 256>>>(h1, W_ih2, b_ih2, b_hh2, xg, MROWS, H4, HSZ);
    }
    lstm_persist4<<<NBLK, 256, SMEM_P4>>>(xg, W_hh2, h2, ctr + TSZ);

    {   // outs = h2 @ lin_W^T + lin_b
        dim3 grid((VSZ + 63) / 64, MROWS / 128);
        tgemm<<<grid, 256>>>(h2, lin_W, lin_b, nullptr, out, MROWS, VSZ, HSZ);
    }
}

// round 7
// speedup vs baseline: 1.7183x; 1.3303x over previous
#include <cuda_runtime.h>
#include <cuda_fp16.h>
#include <math.h>

#define VSZ 5000
#define HSZ 1024
#define ESZ 512
#define BSZ 64
#define TSZ 256
#define H4  (4 * HSZ)
#define MROWS (BSZ * TSZ)   // 16384
#define KP 20               // tgemm padded k-stride

// ---------------- scratch ---------------------------------------------------
__device__ unsigned g_xf[(size_t)TSZ * 4 * 32 * 32 * 4]; // x fp16 A-frags, 16MB
__device__ unsigned g_h1f[4][4 * 64 * 32 * 4];           // h1 frags, 4 bufs x 128KB
__device__ unsigned g_h2f[2][4 * 64 * 32 * 4];           // h2 frags, 2 bufs
__device__ unsigned g_wf2[64 * 8 * 64 * 64];             // W_ih2 fp16 B-frags, 8MB
__device__ float    g_h2[(size_t)MROWS * HSZ];           // h2 fp32 for final GEMM
__device__ unsigned g_ctr[2 * TSZ];

// ---------------- helpers ---------------------------------------------------
__device__ __forceinline__ unsigned f2tf(float x) {
    unsigned u; asm("cvt.rna.tf32.f32 %0, %1;" : "=r"(u) : "f"(x)); return u;
}
__device__ __forceinline__ unsigned pack2(float x, float y) {
    __half2 h = __floats2half2_rn(x, y);
    return *(unsigned*)&h;
}
__device__ __forceinline__ void mma8(float* c, const unsigned* a, const unsigned* b) {
    asm volatile(
        "mma.sync.aligned.m16n8k8.row.col.f32.tf32.tf32.f32 "
        "{%0,%1,%2,%3}, {%4,%5,%6,%7}, {%8,%9}, {%0,%1,%2,%3};\n"
        : "+f"(c[0]), "+f"(c[1]), "+f"(c[2]), "+f"(c[3])
        : "r"(a[0]), "r"(a[1]), "r"(a[2]), "r"(a[3]), "r"(b[0]), "r"(b[1]));
}
__device__ __forceinline__ void mma16(float* c, const unsigned* a, const unsigned* b) {
    asm volatile(
        "mma.sync.aligned.m16n8k16.row.col.f32.f16.f16.f32 "
        "{%0,%1,%2,%3}, {%4,%5,%6,%7}, {%8,%9}, {%0,%1,%2,%3};\n"
        : "+f"(c[0]), "+f"(c[1]), "+f"(c[2]), "+f"(c[3])
        : "r"(a[0]), "r"(a[1]), "r"(a[2]), "r"(a[3]), "r"(b[0]), "r"(b[1]));
}
__device__ __forceinline__ void red_release(unsigned* p) {
    asm volatile("red.release.gpu.global.add.u32 [%0], 1;" :: "l"(p) : "memory");
}
__device__ __forceinline__ unsigned ld_acquire(const unsigned* p) {
    unsigned v;
    asm volatile("ld.acquire.gpu.global.b32 %0, [%1];" : "=r"(v) : "l"(p) : "memory");
    return v;
}

// ---------------- small kernels ----------------------------------------------
__global__ void zero_ctr_kernel() { g_ctr[threadIdx.x] = 0u; }

// embed -> fp16 A fragments, laid out [t][mt][c][lane][e]
__global__ void embed_frag(const int* __restrict__ input,
                           const float* __restrict__ embedW)
{
    int row = blockIdx.x;            // b*TSZ + t
    int b = row >> 8, t = row & 255;
    int idx = input[row];
    int k = threadIdx.x * 4;         // 0..508
    float4 v = *(const float4*)(embedW + (size_t)idx * ESZ + k);
    int mt = b >> 4, ml = b & 15;
    int c = k >> 4, kk = k & 15;
    int e  = ((ml >= 8) ? 1 : 0) + ((kk >= 8) ? 2 : 0);
    int lp = (ml & 7) * 4 + ((kk & 7) >> 1);
    unsigned* base = g_xf + ((size_t)((t * 4 + mt) * 32 + c) * 32) * 4;
    base[lp * 4 + e]       = pack2(v.x, v.y);
    base[(lp + 1) * 4 + e] = pack2(v.z, v.w);
}

// W_ih2 -> fp16 B fragments in global (L2-resident)
__global__ void pack_wf2(const float* __restrict__ Wih2)
{
    int bn = blockIdx.x;             // 0..63
    int h0 = bn * 16;
    for (int idx = threadIdx.x; idx < 64 * 512; idx += 256) {
        int nl = idx >> 9, k = (idx & 511) * 2;
        int g = nl >> 4, u = nl & 15;
        float2 v = *(const float2*)&Wih2[(size_t)(g * HSZ + h0 + u) * HSZ + k];
        int c = k >> 4, kk = k & 15;
        int tn = nl >> 3, rr = nl & 7, qq = (kk & 7) >> 1, f = (kk >= 8) ? 1 : 0;
        g_wf2[((size_t)(bn * 8 + tn) * 64 + c) * 64 + (rr * 4 + qq) * 2 + f] = pack2(v.x, v.y);
    }
}

// ---------------- dual-layer pipelined persistent LSTM ----------------------
// 128 blocks: 0..63 = layer1 (W_ih1+W_hh1 in SMEM, K=512+1024),
//             64..127 = layer2 (W_hh2 in SMEM, W_ih2 frags from L2, K=1024+1024).
// Each block: all 64 batch rows x 64 gate cols (16 h-units x 4 gates).
// 8 warps = 4m x 2n; warp tile 16 rows x 32 cols, full K.
__global__ void __launch_bounds__(256, 1)
lstm_dual(const float* __restrict__ Wih1, const float* __restrict__ Whh1,
          const float* __restrict__ bi1,  const float* __restrict__ bh1,
          const float* __restrict__ Whh2,
          const float* __restrict__ bi2,  const float* __restrict__ bh2)
{
    extern __shared__ unsigned smu[];
    const int tid = threadIdx.x, lane = tid & 31, wid = tid >> 5;
    const int mw = wid & 3, nw = wid >> 2;
    const bool isL2 = (blockIdx.x >= 64);
    const int bn = isL2 ? (blockIdx.x - 64) : blockIdx.x;
    const int h0 = bn * 16;
    unsigned* l1c = g_ctr;
    unsigned* l2c = g_ctr + TSZ;

    float* Gb;
    if (!isL2) {
        unsigned* Wp = smu;                       // [8tn][96c][64w] = 49152 words
        Gb = (float*)(smu + 8 * 96 * 64);
        for (int idx = tid; idx < 64 * 768; idx += 256) {
            int nl = idx / 768, kp = idx - nl * 768, k = kp * 2;
            int g = nl >> 4, u = nl & 15;
            float2 v; int c, kk;
            if (k < 512) {
                v = *(const float2*)&Wih1[(size_t)(g * HSZ + h0 + u) * ESZ + k];
                c = k >> 4; kk = k & 15;
            } else {
                int k2 = k - 512;
                v = *(const float2*)&Whh1[(size_t)(g * HSZ + h0 + u) * HSZ + k2];
                c = 32 + (k2 >> 4); kk = k2 & 15;
            }
            int tn = nl >> 3, rr = nl & 7, qq = (kk & 7) >> 1, f = (kk >= 8) ? 1 : 0;
            Wp[((tn * 96 + c) * 32 + rr * 4 + qq) * 2 + f] = pack2(v.x, v.y);
        }
    } else {
        unsigned* Wp = smu;                       // [8tn][64c][64w] = 32768 words
        Gb = (float*)(smu + 8 * 64 * 64);
        for (int idx = tid; idx < 64 * 512; idx += 256) {
            int nl = idx >> 9, k = (idx & 511) * 2;
            int g = nl >> 4, u = nl & 15;
            float2 v = *(const float2*)&Whh2[(size_t)(g * HSZ + h0 + u) * HSZ + k];
            int c = k >> 4, kk = k & 15;
            int tn = nl >> 3, rr = nl & 7, qq = (kk & 7) >> 1, f = (kk >= 8) ? 1 : 0;
            Wp[((tn * 64 + c) * 32 + rr * 4 + qq) * 2 + f] = pack2(v.x, v.y);
        }
    }
    __syncthreads();

    // epilogue mapping: thread -> col jb, rows rg*4..rg*4+3
    const int jb = tid & 15, rg = tid >> 4;
    float bia[4];
    {
        const float* bA = isL2 ? bi2 : bi1;
        const float* bB = isL2 ? bh2 : bh1;
        #pragma unroll
        for (int g = 0; g < 4; g++)
            bia[g] = bA[g * HSZ + h0 + jb] + bB[g * HSZ + h0 + jb];
    }
    int pk[4]; size_t h2a[4];
    #pragma unroll
    for (int i = 0; i < 4; i++) {
        int ri = rg * 4 + i, mt = ri >> 4, ml = ri & 15;
        int lp = (ml & 7) * 4 + ((jb & 7) >> 1);
        int e  = ((ml >= 8) ? 1 : 0) + ((jb >= 8) ? 2 : 0);
        pk[i]  = (((mt * 64 + bn) * 32 + lp) * 4 + e) * 2 + (jb & 1);
        h2a[i] = ((size_t)ri * TSZ) * HSZ + h0 + jb;
    }
    float cst[4] = {0.f, 0.f, 0.f, 0.f};
    const int r = lane >> 2, q = lane & 3;
    const unsigned* wb = smu + lane * 2;

    for (int t = 0; t < TSZ; t++) {
        float acc[4][4];
        #pragma unroll
        for (int i = 0; i < 4; i++)
            #pragma unroll
            for (int j = 0; j < 4; j++) acc[i][j] = 0.f;

        if (!isL2) {
            // ---- x part (no dependency) ----
            const uint4* ax = (const uint4*)g_xf + ((size_t)(t * 4 + mw) * 32) * 32 + lane;
            #pragma unroll 8
            for (int c = 0; c < 32; c++) {
                uint4 a4 = __ldcg(ax + c * 32);
                unsigned af[4] = { a4.x, a4.y, a4.z, a4.w };
                #pragma unroll
                for (int tn = 0; tn < 4; tn++) {
                    const unsigned* p = wb + ((nw * 4 + tn) * 96 + c) * 64;
                    unsigned bg[2] = { p[0], p[1] };
                    mma16(acc[tn], af, bg);
                }
            }
            // ---- h part ----
            if (t > 0) {
                if (tid == 0) {
                    while (ld_acquire(&l1c[t - 1]) < 64) { }
                    if (t >= 4) while (ld_acquire(&l2c[t - 4]) < 64) { }
                }
                __syncthreads();
                const uint4* ah = (const uint4*)g_h1f[(t - 1) & 3] + (mw * 64) * 32 + lane;
                #pragma unroll 8
                for (int c = 0; c < 64; c++) {
                    uint4 a4 = __ldcg(ah + c * 32);
                    unsigned af[4] = { a4.x, a4.y, a4.z, a4.w };
                    #pragma unroll
                    for (int tn = 0; tn < 4; tn++) {
                        const unsigned* p = wb + ((nw * 4 + tn) * 96 + 32 + c) * 64;
                        unsigned bg[2] = { p[0], p[1] };
                        mma16(acc[tn], af, bg);
                    }
                }
            }
        } else {
            // ---- hh part (own chain, usually ready) ----
            if (t > 0) {
                if (tid == 0) { while (ld_acquire(&l2c[t - 1]) < 64) { } }
                __syncthreads();
                const uint4* ah = (const uint4*)g_h2f[(t - 1) & 1] + (mw * 64) * 32 + lane;
                #pragma unroll 8
                for (int c = 0; c < 64; c++) {
                    uint4 a4 = __ldcg(ah + c * 32);
                    unsigned af[4] = { a4.x, a4.y, a4.z, a4.w };
                    #pragma unroll
                    for (int tn = 0; tn < 4; tn++) {
                        const unsigned* p = wb + ((nw * 4 + tn) * 64 + c) * 64;
                        unsigned bg[2] = { p[0], p[1] };
                        mma16(acc[tn], af, bg);
                    }
                }
            }
            // ---- ih part (waits on layer-1 step t) ----
            if (tid == 0) { while (ld_acquire(&l1c[t]) < 64) { } }
            __syncthreads();
            const uint4* ah1 = (const uint4*)g_h1f[t & 3] + (mw * 64) * 32 + lane;
            const unsigned* wg = g_wf2 + ((size_t)(bn * 8 + nw * 4) * 64) * 64 + lane * 2;
            #pragma unroll 8
            for (int c = 0; c < 64; c++) {
                uint4 a4 = __ldcg(ah1 + c * 32);
                unsigned af[4] = { a4.x, a4.y, a4.z, a4.w };
                #pragma unroll
                for (int tn = 0; tn < 4; tn++) {
                    const uint2 b2 = __ldg((const uint2*)(wg + ((size_t)tn * 64 + c) * 64));
                    unsigned bg[2] = { b2.x, b2.y };
                    mma16(acc[tn], af, bg);
                }
            }
        }

        // ---- stage accumulators ----
        #pragma unroll
        for (int tn = 0; tn < 4; tn++) {
            int col = nw * 32 + tn * 8 + 2 * q;
            Gb[(mw * 16 + r    ) * 68 + col]     = acc[tn][0];
            Gb[(mw * 16 + r    ) * 68 + col + 1] = acc[tn][1];
            Gb[(mw * 16 + r + 8) * 68 + col]     = acc[tn][2];
            Gb[(mw * 16 + r + 8) * 68 + col + 1] = acc[tn][3];
        }
        __syncthreads();

        // ---- cell update ----
        __half* hfo = (__half*)(isL2 ? g_h2f[t & 1] : g_h1f[t & 3]);
        #pragma unroll
        for (int i = 0; i < 4; i++) {
            int ri = rg * 4 + i;
            float iv = Gb[ri * 68 +      jb] + bia[0];
            float fv = Gb[ri * 68 + 16 + jb] + bia[1];
            float gv = Gb[ri * 68 + 32 + jb] + bia[2];
            float ov = Gb[ri * 68 + 48 + jb] + bia[3];
            float si = 1.f / (1.f + expf(-iv));
            float sf = 1.f / (1.f + expf(-fv));
            float so = 1.f / (1.f + expf(-ov));
            float cn = sf * cst[i] + si * tanhf(gv);
            float hn = so * tanhf(cn);
            cst[i] = cn;
            hfo[pk[i]] = __float2half_rn(hn);
            if (isL2) g_h2[h2a[i] + (size_t)t * HSZ] = hn;
        }
        __threadfence();
        __syncthreads();
        if (tid == 0) red_release(isL2 ? &l2c[t] : &l1c[t]);
    }
}

// ---------------- tf32 tensor GEMM (r4 version, final projection) ----------
__global__ void __launch_bounds__(256, 2)
tgemm(const float* __restrict__ A, const float* __restrict__ W,
      const float* __restrict__ b0v, const float* __restrict__ b1v,
      float* __restrict__ C, int M, int N, int K)
{
    __shared__ unsigned As[2][128][KP];
    __shared__ unsigned Ws[2][64][KP];

    const int tid = threadIdx.x, lane = tid & 31, wid = tid >> 5;
    const int m0 = blockIdx.y * 128, n0 = blockIdx.x * 64;
    const int wm = (wid >> 1) * 32, wn = (wid & 1) * 32;
    const int r = lane >> 2, q = lane & 3;

    float acc[2][4][4];
    #pragma unroll
    for (int i = 0; i < 2; i++)
        #pragma unroll
        for (int j = 0; j < 4; j++)
            #pragma unroll
            for (int k = 0; k < 4; k++) acc[i][j][k] = 0.f;

    const int NIT = K / 16;

    float4 aR[2]; float4 bR;
    const int arow0 = tid >> 2;
    const int akg   = (tid & 3) * 4;
    const int bnl   = tid >> 2;
    const int wrow  = n0 + bnl;
    const bool wok  = (wrow < N);

    {
        aR[0] = *(const float4*)&A[(size_t)(m0 + arow0) * K + akg];
        aR[1] = *(const float4*)&A[(size_t)(m0 + 64 + arow0) * K + akg];
        bR = wok ? *(const float4*)&W[(size_t)wrow * K + akg] : make_float4(0,0,0,0);
        unsigned* s0 = &As[0][arow0][akg];
        s0[0]=f2tf(aR[0].x); s0[1]=f2tf(aR[0].y); s0[2]=f2tf(aR[0].z); s0[3]=f2tf(aR[0].w);
        unsigned* s1 = &As[0][64 + arow0][akg];
        s1[0]=f2tf(aR[1].x); s1[1]=f2tf(aR[1].y); s1[2]=f2tf(aR[1].z); s1[3]=f2tf(aR[1].w);
        unsigned* sw = &Ws[0][bnl][akg];
        sw[0]=f2tf(bR.x); sw[1]=f2tf(bR.y); sw[2]=f2tf(bR.z); sw[3]=f2tf(bR.w);
    }
    __syncthreads();

    for (int it = 0; it < NIT; ++it) {
        if (it + 1 < NIT) {
            int k0 = (it + 1) * 16;
            aR[0] = *(const float4*)&A[(size_t)(m0 + arow0) * K + k0 + akg];
            aR[1] = *(const float4*)&A[(size_t)(m0 + 64 + arow0) * K + k0 + akg];
            bR = wok ? *(const float4*)&W[(size_t)wrow * K + k0 + akg] : make_float4(0,0,0,0);
        }
        const int bf = it & 1;
        #pragma unroll
        for (int kc = 0; kc < 16; kc += 8) {
            unsigned af[2][4];
            #pragma unroll
            for (int tm = 0; tm < 2; tm++) {
                af[tm][0] = As[bf][wm + tm*16 + r    ][kc + q];
                af[tm][1] = As[bf][wm + tm*16 + r + 8][kc + q];
                af[tm][2] = As[bf][wm + tm*16 + r    ][kc + q + 4];
                af[tm][3] = As[bf][wm + tm*16 + r + 8][kc + q + 4];
            }
            unsigned bg[4][2];
            #pragma unroll
            for (int tn = 0; tn < 4; tn++) {
                bg[tn][0] = Ws[bf][wn + tn*8 + r][kc + q];
                bg[tn][1] = Ws[bf][wn + tn*8 + r][kc + q + 4];
            }
            #pragma unroll
            for (int tm = 0; tm < 2; tm++)
                #pragma unroll
                for (int tn = 0; tn < 4; tn++)
                    mma8(acc[tm][tn], af[tm], bg[tn]);
        }
        if (it + 1 < NIT) {
            const int nb = (it + 1) & 1;
            unsigned* s0 = &As[nb][arow0][akg];
            s0[0]=f2tf(aR[0].x); s0[1]=f2tf(aR[0].y); s0[2]=f2tf(aR[0].z); s0[3]=f2tf(aR[0].w);
            unsigned* s1 = &As[nb][64 + arow0][akg];
            s1[0]=f2tf(aR[1].x); s1[1]=f2tf(aR[1].y); s1[2]=f2tf(aR[1].z); s1[3]=f2tf(aR[1].w);
            unsigned* sw = &Ws[nb][bnl][akg];
            sw[0]=f2tf(bR.x); sw[1]=f2tf(bR.y); sw[2]=f2tf(bR.z); sw[3]=f2tf(bR.w);
        }
        __syncthreads();
    }

    #pragma unroll
    for (int tm = 0; tm < 2; tm++) {
        #pragma unroll
        for (int tn = 0; tn < 4; tn++) {
            int n = n0 + wn + tn*8 + 2*q;
            float bb0 = 0.f, bb1 = 0.f;
            if (n < N)     bb0 = b0v[n]     + (b1v ? b1v[n]     : 0.f);
            if (n + 1 < N) bb1 = b0v[n + 1] + (b1v ? b1v[n + 1] : 0.f);
            int m = m0 + wm + tm*16 + r;
            if (n < N) {
                C[(size_t)m * N + n]       = acc[tm][tn][0] + bb0;
                C[(size_t)(m+8) * N + n]   = acc[tm][tn][2] + bb0;
            }
            if (n + 1 < N) {
                C[(size_t)m * N + n + 1]     = acc[tm][tn][1] + bb1;
                C[(size_t)(m+8) * N + n + 1] = acc[tm][tn][3] + bb1;
            }
        }
    }
}

// ---------------- launch ----------------------------------------------------
#define SMEM_DUAL ((8 * 96 * 64 + 64 * 68) * 4)   // 214016 bytes (layer1 worst case)

extern "C" void kernel_launch(void* const* d_in, const int* in_sizes, int n_in,
                              void* d_out, int out_size)
{
    const int*   input  = (const int*)  d_in[0];
    const float* embedW = (const float*)d_in[2];
    const float* W_ih1  = (const float*)d_in[3];
    const float* W_hh1  = (const float*)d_in[4];
    const float* b_ih1  = (const float*)d_in[5];
    const float* b_hh1  = (const float*)d_in[6];
    const float* W_ih2  = (const float*)d_in[7];
    const float* W_hh2  = (const float*)d_in[8];
    const float* b_ih2  = (const float*)d_in[9];
    const float* b_hh2  = (const float*)d_in[10];
    const float* lin_W  = (const float*)d_in[11];
    const float* lin_b  = (const float*)d_in[12];
    float* out = (float*)d_out;

    float* h2;
    cudaGetSymbolAddress((void**)&h2, g_h2);

    cudaFuncSetAttribute(lstm_dual,
                         cudaFuncAttributeMaxDynamicSharedMemorySize, SMEM_DUAL);

    zero_ctr_kernel<<<1, 2 * TSZ>>>();
    embed_frag<<<MROWS, 128>>>(input, embedW);
    pack_wf2<<<64, 256>>>(W_ih2);

    lstm_dual<<<128, 256, SMEM_DUAL>>>(W_ih1, W_hh1, b_ih1, b_hh1,
                                       W_hh2, b_ih2, b_hh2);

    {   // outs = h2 @ lin_W^T + lin_b
        dim3 grid((VSZ + 63) / 64, MROWS / 128);
        tgemm<<<grid, 256>>>(h2, lin_W, lin_b, nullptr, out, MROWS, VSZ, HSZ);
    }
}

// round 8
// speedup vs baseline: 1.8827x; 1.0957x over previous
#include <cuda_runtime.h>
#include <cuda_fp16.h>
#include <math.h>

#define VSZ 5000
#define HSZ 1024
#define ESZ 512
#define BSZ 64
#define TSZ 256
#define H4  (4 * HSZ)
#define MROWS (BSZ * TSZ)   // 16384
#define KP 20               // tgemm padded k-stride

// ---------------- scratch ---------------------------------------------------
__device__ unsigned g_xf[(size_t)TSZ * 4 * 32 * 32 * 4]; // x fp16 A-frags
__device__ unsigned g_h1f[8][4 * 64 * 32 * 4];           // h1 frags, 8 bufs
__device__ unsigned g_h2f[2][4 * 64 * 32 * 4];           // h2 frags, 2 bufs
__device__ unsigned g_wf2[64 * 8 * 64 * 64];             // W_ih2 fp16 B-frags
__device__ float    g_h2[(size_t)MROWS * HSZ];           // h2 fp32 for final GEMM
__device__ unsigned g_ctr[2 * TSZ];

// ---------------- helpers ---------------------------------------------------
__device__ __forceinline__ unsigned f2tf(float x) {
    unsigned u; asm("cvt.rna.tf32.f32 %0, %1;" : "=r"(u) : "f"(x)); return u;
}
__device__ __forceinline__ unsigned pack2(float x, float y) {
    __half2 h = __floats2half2_rn(x, y);
    return *(unsigned*)&h;
}
__device__ __forceinline__ void mma8(float* c, const unsigned* a, const unsigned* b) {
    asm volatile(
        "mma.sync.aligned.m16n8k8.row.col.f32.tf32.tf32.f32 "
        "{%0,%1,%2,%3}, {%4,%5,%6,%7}, {%8,%9}, {%0,%1,%2,%3};\n"
        : "+f"(c[0]), "+f"(c[1]), "+f"(c[2]), "+f"(c[3])
        : "r"(a[0]), "r"(a[1]), "r"(a[2]), "r"(a[3]), "r"(b[0]), "r"(b[1]));
}
__device__ __forceinline__ void mma16(float* c, const unsigned* a, const unsigned* b) {
    asm volatile(
        "mma.sync.aligned.m16n8k16.row.col.f32.f16.f16.f32 "
        "{%0,%1,%2,%3}, {%4,%5,%6,%7}, {%8,%9}, {%0,%1,%2,%3};\n"
        : "+f"(c[0]), "+f"(c[1]), "+f"(c[2]), "+f"(c[3])
        : "r"(a[0]), "r"(a[1]), "r"(a[2]), "r"(a[3]), "r"(b[0]), "r"(b[1]));
}
__device__ __forceinline__ void red_release(unsigned* p) {
    asm volatile("red.release.gpu.global.add.u32 [%0], 1;" :: "l"(p) : "memory");
}
__device__ __forceinline__ unsigned ld_acquire(const unsigned* p) {
    unsigned v;
    asm volatile("ld.acquire.gpu.global.b32 %0, [%1];" : "=r"(v) : "l"(p) : "memory");
    return v;
}
#define BARG1() asm volatile("bar.sync 1, 128;" ::: "memory")
#define BARG2() asm volatile("bar.sync 2, 128;" ::: "memory")

// ---------------- small kernels ----------------------------------------------
__global__ void zero_ctr_kernel() { g_ctr[threadIdx.x] = 0u; }

__global__ void embed_frag(const int* __restrict__ input,
                           const float* __restrict__ embedW)
{
    int row = blockIdx.x;            // b*TSZ + t
    int b = row >> 8, t = row & 255;
    int idx = input[row];
    int k = threadIdx.x * 4;
    float4 v = *(const float4*)(embedW + (size_t)idx * ESZ + k);
    int mt = b >> 4, ml = b & 15;
    int c = k >> 4, kk = k & 15;
    int e  = ((ml >= 8) ? 1 : 0) + ((kk >= 8) ? 2 : 0);
    int lp = (ml & 7) * 4 + ((kk & 7) >> 1);
    unsigned* base = g_xf + ((size_t)((t * 4 + mt) * 32 + c) * 32) * 4;
    base[lp * 4 + e]       = pack2(v.x, v.y);
    base[(lp + 1) * 4 + e] = pack2(v.z, v.w);
}

__global__ void pack_wf2(const float* __restrict__ Wih2)
{
    int bn = blockIdx.x, h0 = bn * 16;
    for (int idx = threadIdx.x; idx < 64 * 512; idx += 256) {
        int nl = idx >> 9, k = (idx & 511) * 2;
        int g = nl >> 4, u = nl & 15;
        float2 v = *(const float2*)&Wih2[(size_t)(g * HSZ + h0 + u) * HSZ + k];
        int c = k >> 4, kk = k & 15;
        int tn = nl >> 3, rr = nl & 7, qq = (kk & 7) >> 1, f = (kk >= 8) ? 1 : 0;
        g_wf2[((size_t)(bn * 8 + tn) * 64 + c) * 64 + (rr * 4 + qq) * 2 + f] = pack2(v.x, v.y);
    }
}

// ---------------- dual-layer, warp-specialized persistent LSTM --------------
// 128 blocks: 0..63 layer1, 64..127 layer2. 8 warps = 2 role-groups x 4 m-tiles.
// L1: role0 = x-part (K=512, no dep), role1 = h-part (K=1024, waits l1c[t-1]).
// L2: role0 = hh (K=1024, waits l2c[t-1]), role1 = ih (K=1024, waits l1c[t]).
__global__ void __launch_bounds__(256, 1)
lstm_dual(const float* __restrict__ Wih1, const float* __restrict__ Whh1,
          const float* __restrict__ bi1,  const float* __restrict__ bh1,
          const float* __restrict__ Whh2,
          const float* __restrict__ bi2,  const float* __restrict__ bh2)
{
    extern __shared__ unsigned smu[];
    const int tid = threadIdx.x, lane = tid & 31, wid = tid >> 5;
    const int mt = wid & 3;               // m-tile 0..3
    const int role = wid >> 2;            // 0 / 1
    const bool isL2 = (blockIdx.x >= 64);
    const int bn = isL2 ? (blockIdx.x - 64) : blockIdx.x;
    const int h0 = bn * 16;
    unsigned* l1c = g_ctr;
    unsigned* l2c = g_ctr + TSZ;

    float* Gb;   // [2 roles][64 rows][68]
    if (!isL2) {
        // Wx frags at [0..16384), Whh1 frags at [16384..49152)
        Gb = (float*)(smu + 49152);
        for (int idx = tid; idx < 64 * 256; idx += 256) {
            int nl = idx >> 8, k = (idx & 255) * 2;
            int g = nl >> 4, u = nl & 15;
            float2 v = *(const float2*)&Wih1[(size_t)(g * HSZ + h0 + u) * ESZ + k];
            int c = k >> 4, kk = k & 15;
            int tn = nl >> 3, rr = nl & 7, qq = (kk & 7) >> 1, f = (kk >= 8) ? 1 : 0;
            smu[((tn * 32 + c) * 32 + rr * 4 + qq) * 2 + f] = pack2(v.x, v.y);
        }
        for (int idx = tid; idx < 64 * 512; idx += 256) {
            int nl = idx >> 9, k = (idx & 511) * 2;
            int g = nl >> 4, u = nl & 15;
            float2 v = *(const float2*)&Whh1[(size_t)(g * HSZ + h0 + u) * HSZ + k];
            int c = k >> 4, kk = k & 15;
            int tn = nl >> 3, rr = nl & 7, qq = (kk & 7) >> 1, f = (kk >= 8) ? 1 : 0;
            smu[16384 + ((tn * 64 + c) * 32 + rr * 4 + qq) * 2 + f] = pack2(v.x, v.y);
        }
    } else {
        // Whh2 frags at [0..32768)
        Gb = (float*)(smu + 32768);
        for (int idx = tid; idx < 64 * 512; idx += 256) {
            int nl = idx >> 9, k = (idx & 511) * 2;
            int g = nl >> 4, u = nl & 15;
            float2 v = *(const float2*)&Whh2[(size_t)(g * HSZ + h0 + u) * HSZ + k];
            int c = k >> 4, kk = k & 15;
            int tn = nl >> 3, rr = nl & 7, qq = (kk & 7) >> 1, f = (kk >= 8) ? 1 : 0;
            smu[((tn * 64 + c) * 32 + rr * 4 + qq) * 2 + f] = pack2(v.x, v.y);
        }
    }
    __syncthreads();

    // epilogue mapping
    const int jb = tid & 15, rg = tid >> 4;
    float bia[4];
    {
        const float* bA = isL2 ? bi2 : bi1;
        const float* bB = isL2 ? bh2 : bh1;
        #pragma unroll
        for (int g = 0; g < 4; g++)
            bia[g] = bA[g * HSZ + h0 + jb] + bB[g * HSZ + h0 + jb];
    }
    int pk[4]; size_t h2a[4];
    #pragma unroll
    for (int i = 0; i < 4; i++) {
        int ri = rg * 4 + i, mti = ri >> 4, ml = ri & 15;
        int lp = (ml & 7) * 4 + ((jb & 7) >> 1);
        int e  = ((ml >= 8) ? 1 : 0) + ((jb >= 8) ? 2 : 0);
        pk[i]  = (((mti * 64 + bn) * 32 + lp) * 4 + e) * 2 + (jb & 1);
        h2a[i] = ((size_t)ri * TSZ) * HSZ + h0 + jb;
    }
    float cst[4] = {0.f, 0.f, 0.f, 0.f};
    const int r = lane >> 2, q = lane & 3;

    for (int t = 0; t < TSZ; t++) {
        float acc[8][4];
        #pragma unroll
        for (int i = 0; i < 8; i++)
            #pragma unroll
            for (int j = 0; j < 4; j++) acc[i][j] = 0.f;

        if (!isL2) {
            if (role == 0) {
                // x-part: K=512, no dependency
                const uint4* ax = (const uint4*)g_xf + ((size_t)(t * 4 + mt) * 32) * 32 + lane;
                #pragma unroll 8
                for (int c = 0; c < 32; c++) {
                    uint4 a4 = __ldcg(ax + c * 32);
                    unsigned af[4] = { a4.x, a4.y, a4.z, a4.w };
                    #pragma unroll
                    for (int tn = 0; tn < 8; tn++) {
                        const unsigned* p = smu + (tn * 32 + c) * 64 + lane * 2;
                        unsigned bg[2] = { p[0], p[1] };
                        mma16(acc[tn], af, bg);
                    }
                }
            } else if (t > 0) {
                if (tid == 128) {
                    while (ld_acquire(&l1c[t - 1]) < 64) { }
                    if (t >= 8) while (ld_acquire(&l2c[t - 8]) < 64) { }
                }
                BARG2();
                const uint4* ah = (const uint4*)g_h1f[(t - 1) & 7] + (mt * 64) * 32 + lane;
                #pragma unroll 8
                for (int c = 0; c < 64; c++) {
                    uint4 a4 = __ldcg(ah + c * 32);
                    unsigned af[4] = { a4.x, a4.y, a4.z, a4.w };
                    #pragma unroll
                    for (int tn = 0; tn < 8; tn++) {
                        const unsigned* p = smu + 16384 + (tn * 64 + c) * 64 + lane * 2;
                        unsigned bg[2] = { p[0], p[1] };
                        mma16(acc[tn], af, bg);
                    }
                }
            }
        } else {
            if (role == 0) {
                // hh-part
                if (t > 0) {
                    if (tid == 0) { while (ld_acquire(&l2c[t - 1]) < 64) { } }
                    BARG1();
                    const uint4* ah = (const uint4*)g_h2f[(t - 1) & 1] + (mt * 64) * 32 + lane;
                    #pragma unroll 8
                    for (int c = 0; c < 64; c++) {
                        uint4 a4 = __ldcg(ah + c * 32);
                        unsigned af[4] = { a4.x, a4.y, a4.z, a4.w };
                        #pragma unroll
                        for (int tn = 0; tn < 8; tn++) {
                            const unsigned* p = smu + (tn * 64 + c) * 64 + lane * 2;
                            unsigned bg[2] = { p[0], p[1] };
                            mma16(acc[tn], af, bg);
                        }
                    }
                }
            } else {
                // ih-part: waits on layer-1 step t
                if (tid == 128) { while (ld_acquire(&l1c[t]) < 64) { } }
                BARG2();
                const uint4* ah1 = (const uint4*)g_h1f[t & 7] + (mt * 64) * 32 + lane;
                const unsigned* wg = g_wf2 + ((size_t)(bn * 8) * 64) * 64 + lane * 2;
                #pragma unroll 8
                for (int c = 0; c < 64; c++) {
                    uint4 a4 = __ldcg(ah1 + c * 32);
                    unsigned af[4] = { a4.x, a4.y, a4.z, a4.w };
                    #pragma unroll
                    for (int tn = 0; tn < 8; tn++) {
                        const uint2 b2 = __ldg((const uint2*)(wg + ((size_t)(tn * 64 + c)) * 64));
                        unsigned bg[2] = { b2.x, b2.y };
                        mma16(acc[tn], af, bg);
                    }
                }
            }
        }

        // ---- stage partial sums (per role-group) ----
        {
            float* gb = &Gb[role * 64 * 68];
            #pragma unroll
            for (int tn = 0; tn < 8; tn++) {
                int col = tn * 8 + 2 * q;
                gb[(mt * 16 + r    ) * 68 + col]     = acc[tn][0];
                gb[(mt * 16 + r    ) * 68 + col + 1] = acc[tn][1];
                gb[(mt * 16 + r + 8) * 68 + col]     = acc[tn][2];
                gb[(mt * 16 + r + 8) * 68 + col + 1] = acc[tn][3];
            }
        }
        __syncthreads();

        // ---- cell update ----
        __half* hfo = (__half*)(isL2 ? g_h2f[t & 1] : g_h1f[t & 7]);
        #pragma unroll
        for (int i = 0; i < 4; i++) {
            int ri = rg * 4 + i;
            float iv = Gb[ri * 68 +      jb] + Gb[64*68 + ri * 68 +      jb] + bia[0];
            float fv = Gb[ri * 68 + 16 + jb] + Gb[64*68 + ri * 68 + 16 + jb] + bia[1];
            float gv = Gb[ri * 68 + 32 + jb] + Gb[64*68 + ri * 68 + 32 + jb] + bia[2];
            float ov = Gb[ri * 68 + 48 + jb] + Gb[64*68 + ri * 68 + 48 + jb] + bia[3];
            float si = 1.f / (1.f + expf(-iv));
            float sf = 1.f / (1.f + expf(-fv));
            float so = 1.f / (1.f + expf(-ov));
            float cn = sf * cst[i] + si * tanhf(gv);
            float hn = so * tanhf(cn);
            cst[i] = cn;
            hfo[pk[i]] = __float2half_rn(hn);
            if (isL2) g_h2[h2a[i] + (size_t)t * HSZ] = hn;
        }
        __threadfence();
        __syncthreads();
        if (tid == 0) red_release(isL2 ? &l2c[t] : &l1c[t]);
    }
}

// ---------------- tf32 tensor GEMM (final projection) -----------------------
__global__ void __launch_bounds__(256, 2)
tgemm(const float* __restrict__ A, const float* __restrict__ W,
      const float* __restrict__ b0v, const float* __restrict__ b1v,
      float* __restrict__ C, int M, int N, int K)
{
    __shared__ unsigned As[2][128][KP];
    __shared__ unsigned Ws[2][64][KP];

    const int tid = threadIdx.x, lane = tid & 31, wid = tid >> 5;
    const int m0 = blockIdx.y * 128, n0 = blockIdx.x * 64;
    const int wm = (wid >> 1) * 32, wn = (wid & 1) * 32;
    const int r = lane >> 2, q = lane & 3;

    float acc[2][4][4];
    #pragma unroll
    for (int i = 0; i < 2; i++)
        #pragma unroll
        for (int j = 0; j < 4; j++)
            #pragma unroll
            for (int k = 0; k < 4; k++) acc[i][j][k] = 0.f;

    const int NIT = K / 16;

    float4 aR[2]; float4 bR;
    const int arow0 = tid >> 2;
    const int akg   = (tid & 3) * 4;
    const int bnl   = tid >> 2;
    const int wrow  = n0 + bnl;
    const bool wok  = (wrow < N);

    {
        aR[0] = *(const float4*)&A[(size_t)(m0 + arow0) * K + akg];
        aR[1] = *(const float4*)&A[(size_t)(m0 + 64 + arow0) * K + akg];
        bR = wok ? *(const float4*)&W[(size_t)wrow * K + akg] : make_float4(0,0,0,0);
        unsigned* s0 = &As[0][arow0][akg];
        s0[0]=f2tf(aR[0].x); s0[1]=f2tf(aR[0].y); s0[2]=f2tf(aR[0].z); s0[3]=f2tf(aR[0].w);
        unsigned* s1 = &As[0][64 + arow0][akg];
        s1[0]=f2tf(aR[1].x); s1[1]=f2tf(aR[1].y); s1[2]=f2tf(aR[1].z); s1[3]=f2tf(aR[1].w);
        unsigned* sw = &Ws[0][bnl][akg];
        sw[0]=f2tf(bR.x); sw[1]=f2tf(bR.y); sw[2]=f2tf(bR.z); sw[3]=f2tf(bR.w);
    }
    __syncthreads();

    for (int it = 0; it < NIT; ++it) {
        if (it + 1 < NIT) {
            int k0 = (it + 1) * 16;
            aR[0] = *(const float4*)&A[(size_t)(m0 + arow0) * K + k0 + akg];
            aR[1] = *(const float4*)&A[(size_t)(m0 + 64 + arow0) * K + k0 + akg];
            bR = wok ? *(const float4*)&W[(size_t)wrow * K + k0 + akg] : make_float4(0,0,0,0);
        }
        const int bf = it & 1;
        #pragma unroll
        for (int kc = 0; kc < 16; kc += 8) {
            unsigned af[2][4];
            #pragma unroll
            for (int tm = 0; tm < 2; tm++) {
                af[tm][0] = As[bf][wm + tm*16 + r    ][kc + q];
                af[tm][1] = As[bf][wm + tm*16 + r + 8][kc + q];
                af[tm][2] = As[bf][wm + tm*16 + r    ][kc + q + 4];
                af[tm][3] = As[bf][wm + tm*16 + r + 8][kc + q + 4];
            }
            unsigned bg[4][2];
            #pragma unroll
            for (int tn = 0; tn < 4; tn++) {
                bg[tn][0] = Ws[bf][wn + tn*8 + r][kc + q];
                bg[tn][1] = Ws[bf][wn + tn*8 + r][kc + q + 4];
            }
            #pragma unroll
            for (int tm = 0; tm < 2; tm++)
                #pragma unroll
                for (int tn = 0; tn < 4; tn++)
                    mma8(acc[tm][tn], af[tm], bg[tn]);
        }
        if (it + 1 < NIT) {
            const int nb = (it + 1) & 1;
            unsigned* s0 = &As[nb][arow0][akg];
            s0[0]=f2tf(aR[0].x); s0[1]=f2tf(aR[0].y); s0[2]=f2tf(aR[0].z); s0[3]=f2tf(aR[0].w);
            unsigned* s1 = &As[nb][64 + arow0][akg];
            s1[0]=f2tf(aR[1].x); s1[1]=f2tf(aR[1].y); s1[2]=f2tf(aR[1].z); s1[3]=f2tf(aR[1].w);
            unsigned* sw = &Ws[nb][bnl][akg];
            sw[0]=f2tf(bR.x); sw[1]=f2tf(bR.y); sw[2]=f2tf(bR.z); sw[3]=f2tf(bR.w);
        }
        __syncthreads();
    }

    #pragma unroll
    for (int tm = 0; tm < 2; tm++) {
        #pragma unroll
        for (int tn = 0; tn < 4; tn++) {
            int n = n0 + wn + tn*8 + 2*q;
            float bb0 = 0.f, bb1 = 0.f;
            if (n < N)     bb0 = b0v[n]     + (b1v ? b1v[n]     : 0.f);
            if (n + 1 < N) bb1 = b0v[n + 1] + (b1v ? b1v[n + 1] : 0.f);
            int m = m0 + wm + tm*16 + r;
            if (n < N) {
                C[(size_t)m * N + n]       = acc[tm][tn][0] + bb0;
                C[(size_t)(m+8) * N + n]   = acc[tm][tn][2] + bb0;
            }
            if (n + 1 < N) {
                C[(size_t)m * N + n + 1]     = acc[tm][tn][1] + bb1;
                C[(size_t)(m+8) * N + n + 1] = acc[tm][tn][3] + bb1;
            }
        }
    }
}

// ---------------- launch ----------------------------------------------------
#define SMEM_DUAL ((16384 + 32768) * 4 + 2 * 64 * 68 * 4)   // 231424 bytes

extern "C" void kernel_launch(void* const* d_in, const int* in_sizes, int n_in,
                              void* d_out, int out_size)
{
    const int*   input  = (const int*)  d_in[0];
    const float* embedW = (const float*)d_in[2];
    const float* W_ih1  = (const float*)d_in[3];
    const float* W_hh1  = (const float*)d_in[4];
    const float* b_ih1  = (const float*)d_in[5];
    const float* b_hh1  = (const float*)d_in[6];
    const float* W_ih2  = (const float*)d_in[7];
    const float* W_hh2  = (const float*)d_in[8];
    const float* b_ih2  = (const float*)d_in[9];
    const float* b_hh2  = (const float*)d_in[10];
    const float* lin_W  = (const float*)d_in[11];
    const float* lin_b  = (const float*)d_in[12];
    float* out = (float*)d_out;

    float* h2;
    cudaGetSymbolAddress((void**)&h2, g_h2);

    cudaFuncSetAttribute(lstm_dual,
                         cudaFuncAttributeMaxDynamicSharedMemorySize, SMEM_DUAL);

    zero_ctr_kernel<<<1, 2 * TSZ>>>();
    embed_frag<<<MROWS, 128>>>(input, embedW);
    pack_wf2<<<64, 256>>>(W_ih2);

    lstm_dual<<<128, 256, SMEM_DUAL>>>(W_ih1, W_hh1, b_ih1, b_hh1,
                                       W_hh2, b_ih2, b_hh2);

    {   // outs = h2 @ lin_W^T + lin_b
        dim3 grid((VSZ + 63) / 64, MROWS / 128);
        tgemm<<<grid, 256>>>(h2, lin_W, lin_b, nullptr, out, MROWS, VSZ, HSZ);
    }
}

// round 9
// speedup vs baseline: 1.9951x; 1.0597x over previous
#include <cuda_runtime.h>
#include <cuda_fp16.h>
#include <math.h>

#define VSZ 5000
#define HSZ 1024
#define ESZ 512
#define BSZ 64
#define TSZ 256
#define H4  (4 * HSZ)
#define MROWS (BSZ * TSZ)   // 16384
#define KP 20               // tgemm padded k-stride

// ---------------- scratch ---------------------------------------------------
__device__ unsigned g_xf[(size_t)TSZ * 4 * 32 * 32 * 4]; // x fp16 A-frags
__device__ unsigned g_h1f[8][4 * 64 * 32 * 4];           // h1 frags, 8 bufs
__device__ unsigned g_h2f[2][4 * 64 * 32 * 4];           // h2 frags, 2 bufs
__device__ unsigned g_wf1[64 * 8 * 32 * 64];             // W_ih1 fp16 B-frags (4MB)
__device__ unsigned g_wf2[64 * 8 * 64 * 64];             // W_ih2 fp16 B-frags (8MB)
__device__ float    g_h2[(size_t)MROWS * HSZ];           // h2 fp32 for final GEMM
__device__ unsigned g_ctr[2 * TSZ];

// ---------------- helpers ---------------------------------------------------
__device__ __forceinline__ unsigned f2tf(float x) {
    unsigned u; asm("cvt.rna.tf32.f32 %0, %1;" : "=r"(u) : "f"(x)); return u;
}
__device__ __forceinline__ unsigned pack2(float x, float y) {
    __half2 h = __floats2half2_rn(x, y);
    return *(unsigned*)&h;
}
__device__ __forceinline__ void mma8(float* c, const unsigned* a, const unsigned* b) {
    asm volatile(
        "mma.sync.aligned.m16n8k8.row.col.f32.tf32.tf32.f32 "
        "{%0,%1,%2,%3}, {%4,%5,%6,%7}, {%8,%9}, {%0,%1,%2,%3};\n"
        : "+f"(c[0]), "+f"(c[1]), "+f"(c[2]), "+f"(c[3])
        : "r"(a[0]), "r"(a[1]), "r"(a[2]), "r"(a[3]), "r"(b[0]), "r"(b[1]));
}
__device__ __forceinline__ void mma16(float* c, const unsigned* a, const unsigned* b) {
    asm volatile(
        "mma.sync.aligned.m16n8k16.row.col.f32.f16.f16.f32 "
        "{%0,%1,%2,%3}, {%4,%5,%6,%7}, {%8,%9}, {%0,%1,%2,%3};\n"
        : "+f"(c[0]), "+f"(c[1]), "+f"(c[2]), "+f"(c[3])
        : "r"(a[0]), "r"(a[1]), "r"(a[2]), "r"(a[3]), "r"(b[0]), "r"(b[1]));
}
__device__ __forceinline__ void red_release(unsigned* p) {
    asm volatile("red.release.gpu.global.add.u32 [%0], 1;" :: "l"(p) : "memory");
}
__device__ __forceinline__ unsigned ld_acquire(const unsigned* p) {
    unsigned v;
    asm volatile("ld.acquire.gpu.global.b32 %0, [%1];" : "=r"(v) : "l"(p) : "memory");
    return v;
}
__device__ __forceinline__ float sigm(float x) { return 1.f / (1.f + __expf(-x)); }
#define BARG1() asm volatile("bar.sync 1, 256;" ::: "memory")
#define BARG2() asm volatile("bar.sync 2, 256;" ::: "memory")

// ---------------- small kernels ----------------------------------------------
__global__ void zero_ctr_kernel() { g_ctr[threadIdx.x] = 0u; }

__global__ void embed_frag(const int* __restrict__ input,
                           const float* __restrict__ embedW)
{
    int row = blockIdx.x;            // b*TSZ + t
    int b = row >> 8, t = row & 255;
    int idx = input[row];
    int k = threadIdx.x * 4;
    float4 v = *(const float4*)(embedW + (size_t)idx * ESZ + k);
    int mt = b >> 4, ml = b & 15;
    int c = k >> 4, kk = k & 15;
    int e  = ((ml >= 8) ? 1 : 0) + ((kk >= 8) ? 2 : 0);
    int lp = (ml & 7) * 4 + ((kk & 7) >> 1);
    unsigned* base = g_xf + ((size_t)((t * 4 + mt) * 32 + c) * 32) * 4;
    base[lp * 4 + e]       = pack2(v.x, v.y);
    base[(lp + 1) * 4 + e] = pack2(v.z, v.w);
}

__global__ void pack_wf1(const float* __restrict__ Wih1)
{
    int bn = blockIdx.x, h0 = bn * 16;
    for (int idx = threadIdx.x; idx < 64 * 256; idx += 256) {
        int nl = idx >> 8, k = (idx & 255) * 2;
        int g = nl >> 4, u = nl & 15;
        float2 v = *(const float2*)&Wih1[(size_t)(g * HSZ + h0 + u) * ESZ + k];
        int c = k >> 4, kk = k & 15;
        int tn = nl >> 3, rr = nl & 7, qq = (kk & 7) >> 1, f = (kk >= 8) ? 1 : 0;
        g_wf1[((size_t)(bn * 8 + tn) * 32 + c) * 64 + (rr * 4 + qq) * 2 + f] = pack2(v.x, v.y);
    }
}

__global__ void pack_wf2(const float* __restrict__ Wih2)
{
    int bn = blockIdx.x, h0 = bn * 16;
    for (int idx = threadIdx.x; idx < 64 * 512; idx += 256) {
        int nl = idx >> 9, k = (idx & 511) * 2;
        int g = nl >> 4, u = nl & 15;
        float2 v = *(const float2*)&Wih2[(size_t)(g * HSZ + h0 + u) * HSZ + k];
        int c = k >> 4, kk = k & 15;
        int tn = nl >> 3, rr = nl & 7, qq = (kk & 7) >> 1, f = (kk >= 8) ? 1 : 0;
        g_wf2[((size_t)(bn * 8 + tn) * 64 + c) * 64 + (rr * 4 + qq) * 2 + f] = pack2(v.x, v.y);
    }
}

// ---------------- dual-layer, warp-specialized persistent LSTM --------------
// 128 blocks x 512 threads. 16 warps = 2 roles x 4 m-tiles x 2 k-halves.
// L1: role0 = x-part (K=512, W from L2, no dep), role1 = h-part (Whh1 SMEM).
// L2: role0 = hh (Whh2 SMEM, waits l2c[t-1]),   role1 = ih (W from L2, waits l1c[t]).
__global__ void __launch_bounds__(512, 1)
lstm_dual(const float* __restrict__ Whh1,
          const float* __restrict__ bi1,  const float* __restrict__ bh1,
          const float* __restrict__ Whh2,
          const float* __restrict__ bi2,  const float* __restrict__ bh2)
{
    extern __shared__ unsigned smu[];
    float* Gb = (float*)(smu + 32768);    // [4 grp][64][68]
    const int tid = threadIdx.x, lane = tid & 31, wid = tid >> 5;
    const int mt = wid & 3;               // m-tile 0..3
    const int kh = (wid >> 2) & 1;        // k-half
    const int role = wid >> 3;            // 0 / 1
    const int grp = role * 2 + kh;
    const bool isL2 = (blockIdx.x >= 64);
    const int bn = isL2 ? (blockIdx.x - 64) : blockIdx.x;
    const int h0 = bn * 16;
    unsigned* l1c = g_ctr;
    unsigned* l2c = g_ctr + TSZ;

    // ---- load W_hh slice into SMEM fp16 B-frags (once) ----
    {
        const float* Whh = isL2 ? Whh2 : Whh1;
        for (int idx = tid; idx < 64 * 512; idx += 512) {
            int nl = idx >> 9, k = (idx & 511) * 2;
            int g = nl >> 4, u = nl & 15;
            float2 v = *(const float2*)&Whh[(size_t)(g * HSZ + h0 + u) * HSZ + k];
            int c = k >> 4, kk = k & 15;
            int tn = nl >> 3, rr = nl & 7, qq = (kk & 7) >> 1, f = (kk >= 8) ? 1 : 0;
            smu[((tn * 64 + c) * 32 + rr * 4 + qq) * 2 + f] = pack2(v.x, v.y);
        }
    }
    __syncthreads();

    // epilogue mapping: thread -> col jb, rows rg*2, rg*2+1
    const int jb = tid & 15, rg = tid >> 4;   // rg 0..31
    float bia[4];
    {
        const float* bA = isL2 ? bi2 : bi1;
        const float* bB = isL2 ? bh2 : bh1;
        #pragma unroll
        for (int g = 0; g < 4; g++)
            bia[g] = bA[g * HSZ + h0 + jb] + bB[g * HSZ + h0 + jb];
    }
    int pk[2]; size_t h2a[2];
    #pragma unroll
    for (int i = 0; i < 2; i++) {
        int ri = rg * 2 + i, mti = ri >> 4, ml = ri & 15;
        int lp = (ml & 7) * 4 + ((jb & 7) >> 1);
        int e  = ((ml >= 8) ? 1 : 0) + ((jb >= 8) ? 2 : 0);
        pk[i]  = (((mti * 64 + bn) * 32 + lp) * 4 + e) * 2 + (jb & 1);
        h2a[i] = ((size_t)ri * TSZ) * HSZ + h0 + jb;
    }
    float cst[2] = {0.f, 0.f};
    const int r = lane >> 2, q = lane & 3;

    for (int t = 0; t < TSZ; t++) {
        float acc[8][4];
        #pragma unroll
        for (int i = 0; i < 8; i++)
            #pragma unroll
            for (int j = 0; j < 4; j++) acc[i][j] = 0.f;

        if (!isL2) {
            if (role == 0) {
                // x-part: K=512 -> 16 chunks per k-half, W streamed from L2
                const uint4* ax = (const uint4*)g_xf
                                  + ((size_t)(t * 4 + mt) * 32 + kh * 16) * 32 + lane;
                const unsigned* wg = g_wf1 + ((size_t)(bn * 8) * 32 + kh * 16) * 64 + lane * 2;
                #pragma unroll 4
                for (int c = 0; c < 16; c++) {
                    uint4 a4 = __ldcg(ax + c * 32);
                    unsigned af[4] = { a4.x, a4.y, a4.z, a4.w };
                    #pragma unroll
                    for (int tn = 0; tn < 8; tn++) {
                        const uint2 b2 = __ldg((const uint2*)(wg + ((size_t)tn * 32 + c) * 64));
                        unsigned bg[2] = { b2.x, b2.y };
                        mma16(acc[tn], af, bg);
                    }
                }
            } else if (t > 0) {
                if (tid == 256) {
                    while (ld_acquire(&l1c[t - 1]) < 64) { }
                    if (t >= 8) while (ld_acquire(&l2c[t - 8]) < 64) { }
                }
                BARG2();
                const uint4* ah = (const uint4*)g_h1f[(t - 1) & 7]
                                  + (mt * 64 + kh * 32) * 32 + lane;
                #pragma unroll 4
                for (int c = 0; c < 32; c++) {
                    uint4 a4 = __ldcg(ah + c * 32);
                    unsigned af[4] = { a4.x, a4.y, a4.z, a4.w };
                    #pragma unroll
                    for (int tn = 0; tn < 8; tn++) {
                        const unsigned* p = smu + (tn * 64 + kh * 32 + c) * 64 + lane * 2;
                        unsigned bg[2] = { p[0], p[1] };
                        mma16(acc[tn], af, bg);
                    }
                }
            }
        } else {
            if (role == 0) {
                if (t > 0) {
                    if (tid == 0) { while (ld_acquire(&l2c[t - 1]) < 64) { } }
                    BARG1();
                    const uint4* ah = (const uint4*)g_h2f[(t - 1) & 1]
                                      + (mt * 64 + kh * 32) * 32 + lane;
                    #pragma unroll 4
                    for (int c = 0; c < 32; c++) {
                        uint4 a4 = __ldcg(ah + c * 32);
                        unsigned af[4] = { a4.x, a4.y, a4.z, a4.w };
                        #pragma unroll
                        for (int tn = 0; tn < 8; tn++) {
                            const unsigned* p = smu + (tn * 64 + kh * 32 + c) * 64 + lane * 2;
                            unsigned bg[2] = { p[0], p[1] };
                            mma16(acc[tn], af, bg);
                        }
                    }
                }
            } else {
                if (tid == 256) { while (ld_acquire(&l1c[t]) < 64) { } }
                BARG2();
                const uint4* ah1 = (const uint4*)g_h1f[t & 7]
                                   + (mt * 64 + kh * 32) * 32 + lane;
                const unsigned* wg = g_wf2 + ((size_t)(bn * 8) * 64 + kh * 32) * 64 + lane * 2;
                #pragma unroll 4
                for (int c = 0; c < 32; c++) {
                    uint4 a4 = __ldcg(ah1 + c * 32);
                    unsigned af[4] = { a4.x, a4.y, a4.z, a4.w };
                    #pragma unroll
                    for (int tn = 0; tn < 8; tn++) {
                        const uint2 b2 = __ldg((const uint2*)(wg + ((size_t)tn * 64 + c) * 64));
                        unsigned bg[2] = { b2.x, b2.y };
                        mma16(acc[tn], af, bg);
                    }
                }
            }
        }

        // ---- stage partial sums (per group) ----
        {
            float* gb = &Gb[grp * 64 * 68];
            #pragma unroll
            for (int tn = 0; tn < 8; tn++) {
                int col = tn * 8 + 2 * q;
                gb[(mt * 16 + r    ) * 68 + col]     = acc[tn][0];
                gb[(mt * 16 + r    ) * 68 + col + 1] = acc[tn][1];
                gb[(mt * 16 + r + 8) * 68 + col]     = acc[tn][2];
                gb[(mt * 16 + r + 8) * 68 + col + 1] = acc[tn][3];
            }
        }
        __syncthreads();

        // ---- cell update: 2 rows per thread ----
        __half* hfo = (__half*)(isL2 ? g_h2f[t & 1] : g_h1f[t & 7]);
        #pragma unroll
        for (int i = 0; i < 2; i++) {
            int ri = rg * 2 + i;
            float iv = bia[0], fv = bia[1], gv = bia[2], ov = bia[3];
            #pragma unroll
            for (int g = 0; g < 4; g++) {
                const float* gb = &Gb[g * 64 * 68 + ri * 68];
                iv += gb[jb]; fv += gb[16 + jb]; gv += gb[32 + jb]; ov += gb[48 + jb];
            }
            float si = sigm(iv), sf = sigm(fv), so = sigm(ov);
            float cn = sf * cst[i] + si * tanhf(gv);
            float hn = so * tanhf(cn);
            cst[i] = cn;
            hfo[pk[i]] = __float2half_rn(hn);
            if (isL2) g_h2[h2a[i] + (size_t)t * HSZ] = hn;
        }
        __threadfence();
        __syncthreads();
        if (tid == 0) red_release(isL2 ? &l2c[t] : &l1c[t]);
    }
}

// ---------------- tf32 tensor GEMM (final projection) -----------------------
__global__ void __launch_bounds__(256, 2)
tgemm(const float* __restrict__ A, const float* __restrict__ W,
      const float* __restrict__ b0v, const float* __restrict__ b1v,
      float* __restrict__ C, int M, int N, int K)
{
    __shared__ unsigned As[2][128][KP];
    __shared__ unsigned Ws[2][64][KP];

    const int tid = threadIdx.x, lane = tid & 31, wid = tid >> 5;
    const int m0 = blockIdx.y * 128, n0 = blockIdx.x * 64;
    const int wm = (wid >> 1) * 32, wn = (wid & 1) * 32;
    const int r = lane >> 2, q = lane & 3;

    float acc[2][4][4];
    #pragma unroll
    for (int i = 0; i < 2; i++)
        #pragma unroll
        for (int j = 0; j < 4; j++)
            #pragma unroll
            for (int k = 0; k < 4; k++) acc[i][j][k] = 0.f;

    const int NIT = K / 16;

    float4 aR[2]; float4 bR;
    const int arow0 = tid >> 2;
    const int akg   = (tid & 3) * 4;
    const int bnl   = tid >> 2;
    const int wrow  = n0 + bnl;
    const bool wok  = (wrow < N);

    {
        aR[0] = *(const float4*)&A[(size_t)(m0 + arow0) * K + akg];
        aR[1] = *(const float4*)&A[(size_t)(m0 + 64 + arow0) * K + akg];
        bR = wok ? *(const float4*)&W[(size_t)wrow * K + akg] : make_float4(0,0,0,0);
        unsigned* s0 = &As[0][arow0][akg];
        s0[0]=f2tf(aR[0].x); s0[1]=f2tf(aR[0].y); s0[2]=f2tf(aR[0].z); s0[3]=f2tf(aR[0].w);
        unsigned* s1 = &As[0][64 + arow0][akg];
        s1[0]=f2tf(aR[1].x); s1[1]=f2tf(aR[1].y); s1[2]=f2tf(aR[1].z); s1[3]=f2tf(aR[1].w);
        unsigned* sw = &Ws[0][bnl][akg];
        sw[0]=f2tf(bR.x); sw[1]=f2tf(bR.y); sw[2]=f2tf(bR.z); sw[3]=f2tf(bR.w);
    }
    __syncthreads();

    for (int it = 0; it < NIT; ++it) {
        if (it + 1 < NIT) {
            int k0 = (it + 1) * 16;
            aR[0] = *(const float4*)&A[(size_t)(m0 + arow0) * K + k0 + akg];
            aR[1] = *(const float4*)&A[(size_t)(m0 + 64 + arow0) * K + k0 + akg];
            bR = wok ? *(const float4*)&W[(size_t)wrow * K + k0 + akg] : make_float4(0,0,0,0);
        }
        const int bf = it & 1;
        #pragma unroll
        for (int kc = 0; kc < 16; kc += 8) {
            unsigned af[2][4];
            #pragma unroll
            for (int tm = 0; tm < 2; tm++) {
                af[tm][0] = As[bf][wm + tm*16 + r    ][kc + q];
                af[tm][1] = As[bf][wm + tm*16 + r + 8][kc + q];
                af[tm][2] = As[bf][wm + tm*16 + r    ][kc + q + 4];
                af[tm][3] = As[bf][wm + tm*16 + r + 8][kc + q + 4];
            }
            unsigned bg[4][2];
            #pragma unroll
            for (int tn = 0; tn < 4; tn++) {
                bg[tn][0] = Ws[bf][wn + tn*8 + r][kc + q];
                bg[tn][1] = Ws[bf][wn + tn*8 + r][kc + q + 4];
            }
            #pragma unroll
            for (int tm = 0; tm < 2; tm++)
                #pragma unroll
                for (int tn = 0; tn < 4; tn++)
                    mma8(acc[tm][tn], af[tm], bg[tn]);
        }
        if (it + 1 < NIT) {
            const int nb = (it + 1) & 1;
            unsigned* s0 = &As[nb][arow0][akg];
            s0[0]=f2tf(aR[0].x); s0[1]=f2tf(aR[0].y); s0[2]=f2tf(aR[0].z); s0[3]=f2tf(aR[0].w);
            unsigned* s1 = &As[nb][64 + arow0][akg];
            s1[0]=f2tf(aR[1].x); s1[1]=f2tf(aR[1].y); s1[2]=f2tf(aR[1].z); s1[3]=f2tf(aR[1].w);
            unsigned* sw = &Ws[nb][bnl][akg];
            sw[0]=f2tf(bR.x); sw[1]=f2tf(bR.y); sw[2]=f2tf(bR.z); sw[3]=f2tf(bR.w);
        }
        __syncthreads();
    }

    #pragma unroll
    for (int tm = 0; tm < 2; tm++) {
        #pragma unroll
        for (int tn = 0; tn < 4; tn++) {
            int n = n0 + wn + tn*8 + 2*q;
            float bb0 = 0.f, bb1 = 0.f;
            if (n < N)     bb0 = b0v[n]     + (b1v ? b1v[n]     : 0.f);
            if (n + 1 < N) bb1 = b0v[n + 1] + (b1v ? b1v[n + 1] : 0.f);
            int m = m0 + wm + tm*16 + r;
            if (n < N) {
                C[(size_t)m * N + n]       = acc[tm][tn][0] + bb0;
                C[(size_t)(m+8) * N + n]   = acc[tm][tn][2] + bb0;
            }
            if (n + 1 < N) {
                C[(size_t)m * N + n + 1]     = acc[tm][tn][1] + bb1;
                C[(size_t)(m+8) * N + n + 1] = acc[tm][tn][3] + bb1;
            }
        }
    }
}

// ---------------- launch ----------------------------------------------------
#define SMEM_DUAL (32768 * 4 + 4 * 64 * 68 * 4)   // 200704 bytes

extern "C" void kernel_launch(void* const* d_in, const int* in_sizes, int n_in,
                              void* d_out, int out_size)
{
    const int*   input  = (const int*)  d_in[0];
    const float* embedW = (const float*)d_in[2];
    const float* W_ih1  = (const float*)d_in[3];
    const float* W_hh1  = (const float*)d_in[4];
    const float* b_ih1  = (const float*)d_in[5];
    const float* b_hh1  = (const float*)d_in[6];
    const float* W_ih2  = (const float*)d_in[7];
    const float* W_hh2  = (const float*)d_in[8];
    const float* b_ih2  = (const float*)d_in[9];
    const float* b_hh2  = (const float*)d_in[10];
    const float* lin_W  = (const float*)d_in[11];
    const float* lin_b  = (const float*)d_in[12];
    float* out = (float*)d_out;

    float* h2;
    cudaGetSymbolAddress((void**)&h2, g_h2);

    cudaFuncSetAttribute(lstm_dual,
                         cudaFuncAttributeMaxDynamicSharedMemorySize, SMEM_DUAL);

    zero_ctr_kernel<<<1, 2 * TSZ>>>();
    embed_frag<<<MROWS, 128>>>(input, embedW);
    pack_wf1<<<64, 256>>>(W_ih1);
    pack_wf2<<<64, 256>>>(W_ih2);

    lstm_dual<<<128, 512, SMEM_DUAL>>>(W_hh1, b_ih1, b_hh1,
                                       W_hh2, b_ih2, b_hh2);

    {   // outs = h2 @ lin_W^T + lin_b
        dim3 grid((VSZ + 63) / 64, MROWS / 128);
        tgemm<<<grid, 256>>>(h2, lin_W, lin_b, nullptr, out, MROWS, VSZ, HSZ);
    }
}

// round 12
// speedup vs baseline: 2.9459x; 1.4765x over previous
#include <cuda_runtime.h>
#include <cuda_fp16.h>
#include <math.h>

#define VSZ 5000
#define HSZ 1024
#define ESZ 512
#define BSZ 64
#define TSZ 256
#define H4  (4 * HSZ)
#define MROWS (BSZ * TSZ)   // 16384
#define NTILE 79            // ceil(5000/64)

// ---------------- scratch ---------------------------------------------------
#define FRAGBUF (4 * 64 * 32 * 4)                     // uint32 per step-buffer
__device__ unsigned g_xf[(size_t)TSZ * FRAGBUF / 2];  // x fp16 A-frags (K=512)
__device__ unsigned g_h1f[(size_t)TSZ * FRAGBUF];     // h1 frags, all steps (32MB)
__device__ unsigned g_h2f[(size_t)TSZ * FRAGBUF];     // h2 frags, all steps (32MB)
__device__ unsigned g_wf1[64 * 8 * 32 * 64];          // W_ih1 fp16 B-frags (4MB)
__device__ unsigned g_wf2[64 * 8 * 64 * 64];          // W_ih2 fp16 B-frags (8MB)
__device__ unsigned g_lwf[(size_t)NTILE * 8 * 64 * 64];// lin_W fp16 B-frags (10.4MB)
__device__ unsigned g_ctr[2 * TSZ];

// ---------------- helpers ---------------------------------------------------
__device__ __forceinline__ unsigned pack2(float x, float y) {
    __half2 h = __floats2half2_rn(x, y);
    return *(unsigned*)&h;
}
__device__ __forceinline__ void mma16(float* c, const unsigned* a, const unsigned* b) {
    asm volatile(
        "mma.sync.aligned.m16n8k16.row.col.f32.f16.f16.f32 "
        "{%0,%1,%2,%3}, {%4,%5,%6,%7}, {%8,%9}, {%0,%1,%2,%3};\n"
        : "+f"(c[0]), "+f"(c[1]), "+f"(c[2]), "+f"(c[3])
        : "r"(a[0]), "r"(a[1]), "r"(a[2]), "r"(a[3]), "r"(b[0]), "r"(b[1]));
}
__device__ __forceinline__ void red_release(unsigned* p) {
    asm volatile("red.release.gpu.global.add.u32 [%0], 1;" :: "l"(p) : "memory");
}
__device__ __forceinline__ unsigned ld_acquire(const unsigned* p) {
    unsigned v;
    asm volatile("ld.acquire.gpu.global.b32 %0, [%1];" : "=r"(v) : "l"(p) : "memory");
    return v;
}
__device__ __forceinline__ float sigm(float x) { return 1.f / (1.f + __expf(-x)); }
#define BARG1() asm volatile("bar.sync 1, 256;" ::: "memory")
#define BARG2() asm volatile("bar.sync 2, 256;" ::: "memory")

// ---------------- small kernels ----------------------------------------------
__global__ void zero_ctr_kernel() { g_ctr[threadIdx.x] = 0u; }

__global__ void embed_frag(const int* __restrict__ input,
                           const float* __restrict__ embedW)
{
    int row = blockIdx.x;            // b*TSZ + t
    int b = row >> 8, t = row & 255;
    int idx = input[row];
    int k = threadIdx.x * 4;
    float4 v = *(const float4*)(embedW + (size_t)idx * ESZ + k);
    int mt = b >> 4, ml = b & 15;
    int c = k >> 4, kk = k & 15;
    int e  = ((ml >= 8) ? 1 : 0) + ((kk >= 8) ? 2 : 0);
    int lp = (ml & 7) * 4 + ((kk & 7) >> 1);
    unsigned* base = g_xf + ((size_t)((t * 4 + mt) * 32 + c) * 32) * 4;
    base[lp * 4 + e]       = pack2(v.x, v.y);
    base[(lp + 1) * 4 + e] = pack2(v.z, v.w);
}

__global__ void pack_wf1(const float* __restrict__ Wih1)
{
    int bn = blockIdx.x, h0 = bn * 16;
    for (int idx = threadIdx.x; idx < 64 * 256; idx += 256) {
        int nl = idx >> 8, k = (idx & 255) * 2;
        int g = nl >> 4, u = nl & 15;
        float2 v = *(const float2*)&Wih1[(size_t)(g * HSZ + h0 + u) * ESZ + k];
        int c = k >> 4, kk = k & 15;
        int tn = nl >> 3, rr = nl & 7, qq = (kk & 7) >> 1, f = (kk >= 8) ? 1 : 0;
        g_wf1[((size_t)(bn * 8 + tn) * 32 + c) * 64 + (rr * 4 + qq) * 2 + f] = pack2(v.x, v.y);
    }
}

__global__ void pack_wf2(const float* __restrict__ Wih2)
{
    int bn = blockIdx.x, h0 = bn * 16;
    for (int idx = threadIdx.x; idx < 64 * 512; idx += 256) {
        int nl = idx >> 9, k = (idx & 511) * 2;
        int g = nl >> 4, u = nl & 15;
        float2 v = *(const float2*)&Wih2[(size_t)(g * HSZ + h0 + u) * HSZ + k];
        int c = k >> 4, kk = k & 15;
        int tn = nl >> 3, rr = nl & 7, qq = (kk & 7) >> 1, f = (kk >= 8) ? 1 : 0;
        g_wf2[((size_t)(bn * 8 + tn) * 64 + c) * 64 + (rr * 4 + qq) * 2 + f] = pack2(v.x, v.y);
    }
}

// lin_W (5000 x 1024) -> fp16 B-frags, rows padded with zeros to 79*64
__global__ void pack_lwf(const float* __restrict__ linW)
{
    int nb = blockIdx.x, n0 = nb * 64;
    for (int idx = threadIdx.x; idx < 64 * 512; idx += 256) {
        int nl = idx >> 9, k = (idx & 511) * 2;
        int n = n0 + nl;
        float2 v = make_float2(0.f, 0.f);
        if (n < VSZ) v = *(const float2*)&linW[(size_t)n * HSZ + k];
        int c = k >> 4, kk = k & 15;
        int tn = nl >> 3, rr = nl & 7, qq = (kk & 7) >> 1, f = (kk >= 8) ? 1 : 0;
        g_lwf[((size_t)(nb * 8 + tn) * 64 + c) * 64 + (rr * 4 + qq) * 2 + f] = pack2(v.x, v.y);
    }
}

// ---------------- dual-layer, warp-specialized persistent LSTM --------------
// 128 blocks x 512 threads. 16 warps = 2 roles x 4 m-tiles x 2 k-halves.
__global__ void __launch_bounds__(512, 1)
lstm_dual(const float* __restrict__ Whh1,
          const float* __restrict__ bi1,  const float* __restrict__ bh1,
          const float* __restrict__ Whh2,
          const float* __restrict__ bi2,  const float* __restrict__ bh2)
{
    extern __shared__ unsigned smu[];
    float* Gb = (float*)(smu + 32768);    // [4 grp][64][68]
    const int tid = threadIdx.x, lane = tid & 31, wid = tid >> 5;
    const int mt = wid & 3;
    const int kh = (wid >> 2) & 1;
    const int role = wid >> 3;
    const int grp = role * 2 + kh;
    const bool isL2 = (blockIdx.x >= 64);
    const int bn = isL2 ? (blockIdx.x - 64) : blockIdx.x;
    const int h0 = bn * 16;
    unsigned* l1c = g_ctr;
    unsigned* l2c = g_ctr + TSZ;

    // ---- load W_hh slice into SMEM fp16 B-frags (once) ----
    {
        const float* Whh = isL2 ? Whh2 : Whh1;
        for (int idx = tid; idx < 64 * 512; idx += 512) {
            int nl = idx >> 9, k = (idx & 511) * 2;
            int g = nl >> 4, u = nl & 15;
            float2 v = *(const float2*)&Whh[(size_t)(g * HSZ + h0 + u) * HSZ + k];
            int c = k >> 4, kk = k & 15;
            int tn = nl >> 3, rr = nl & 7, qq = (kk & 7) >> 1, f = (kk >= 8) ? 1 : 0;
            smu[((tn * 64 + c) * 32 + rr * 4 + qq) * 2 + f] = pack2(v.x, v.y);
        }
    }
    __syncthreads();

    // epilogue mapping: thread -> col jb, rows rg*2, rg*2+1
    const int jb = tid & 15, rg = tid >> 4;
    float bia[4];
    {
        const float* bA = isL2 ? bi2 : bi1;
        const float* bB = isL2 ? bh2 : bh1;
        #pragma unroll
        for (int g = 0; g < 4; g++)
            bia[g] = bA[g * HSZ + h0 + jb] + bB[g * HSZ + h0 + jb];
    }
    int pk[2];
    #pragma unroll
    for (int i = 0; i < 2; i++) {
        int ri = rg * 2 + i, mti = ri >> 4, ml = ri & 15;
        int lp = (ml & 7) * 4 + ((jb & 7) >> 1);
        int e  = ((ml >= 8) ? 1 : 0) + ((jb >= 8) ? 2 : 0);
        pk[i]  = (((mti * 64 + bn) * 32 + lp) * 4 + e) * 2 + (jb & 1);
    }
    float cst[2] = {0.f, 0.f};
    const int r = lane >> 2, q = lane & 3;

    for (int t = 0; t < TSZ; t++) {
        float acc[8][4];
        #pragma unroll
        for (int i = 0; i < 8; i++)
            #pragma unroll
            for (int j = 0; j < 4; j++) acc[i][j] = 0.f;

        if (!isL2) {
            if (role == 0) {
                // x-part: K=512, W from L2, no dependency
                const uint4* ax = (const uint4*)g_xf
                                  + ((size_t)(t * 4 + mt) * 32 + kh * 16) * 32 + lane;
                const unsigned* wg = g_wf1 + ((size_t)(bn * 8) * 32 + kh * 16) * 64 + lane * 2;
                #pragma unroll 4
                for (int c = 0; c < 16; c++) {
                    uint4 a4 = __ldcg(ax + c * 32);
                    unsigned af[4] = { a4.x, a4.y, a4.z, a4.w };
                    #pragma unroll
                    for (int tn = 0; tn < 8; tn++) {
                        const uint2 b2 = __ldg((const uint2*)(wg + ((size_t)tn * 32 + c) * 64));
                        unsigned bg[2] = { b2.x, b2.y };
                        mma16(acc[tn], af, bg);
                    }
                }
            } else if (t > 0) {
                if (tid == 256) { while (ld_acquire(&l1c[t - 1]) < 64) { } }
                BARG2();
                const uint4* ah = (const uint4*)g_h1f + (size_t)(t - 1) * (FRAGBUF / 4)
                                  + (mt * 64 + kh * 32) * 32 + lane;
                #pragma unroll 4
                for (int c = 0; c < 32; c++) {
                    uint4 a4 = __ldcg(ah + c * 32);
                    unsigned af[4] = { a4.x, a4.y, a4.z, a4.w };
                    #pragma unroll
                    for (int tn = 0; tn < 8; tn++) {
                        const unsigned* p = smu + (tn * 64 + kh * 32 + c) * 64 + lane * 2;
                        unsigned bg[2] = { p[0], p[1] };
                        mma16(acc[tn], af, bg);
                    }
                }
            }
        } else {
            if (role == 0) {
                if (t > 0) {
                    if (tid == 0) { while (ld_acquire(&l2c[t - 1]) < 64) { } }
                    BARG1();
                    const uint4* ah = (const uint4*)g_h2f + (size_t)(t - 1) * (FRAGBUF / 4)
                                      + (mt * 64 + kh * 32) * 32 + lane;
                    #pragma unroll 4
                    for (int c = 0; c < 32; c++) {
                        uint4 a4 = __ldcg(ah + c * 32);
                        unsigned af[4] = { a4.x, a4.y, a4.z, a4.w };
                        #pragma unroll
                        for (int tn = 0; tn < 8; tn++) {
                            const unsigned* p = smu + (tn * 64 + kh * 32 + c) * 64 + lane * 2;
                            unsigned bg[2] = { p[0], p[1] };
                            mma16(acc[tn], af, bg);
                        }
                    }
                }
            } else {
                if (tid == 256) { while (ld_acquire(&l1c[t]) < 64) { } }
                BARG2();
                const uint4* ah1 = (const uint4*)g_h1f + (size_t)t * (FRAGBUF / 4)
                                   + (mt * 64 + kh * 32) * 32 + lane;
                const unsigned* wg = g_wf2 + ((size_t)(bn * 8) * 64 + kh * 32) * 64 + lane * 2;
                #pragma unroll 4
                for (int c = 0; c < 32; c++) {
                    uint4 a4 = __ldcg(ah1 + c * 32);
                    unsigned af[4] = { a4.x, a4.y, a4.z, a4.w };
                    #pragma unroll
                    for (int tn = 0; tn < 8; tn++) {
                        const uint2 b2 = __ldg((const uint2*)(wg + ((size_t)tn * 64 + c) * 64));
                        unsigned bg[2] = { b2.x, b2.y };
                        mma16(acc[tn], af, bg);
                    }
                }
            }
        }

        // ---- stage partial sums (per group) ----
        {
            float* gb = &Gb[grp * 64 * 68];
            #pragma unroll
            for (int tn = 0; tn < 8; tn++) {
                int col = tn * 8 + 2 * q;
                gb[(mt * 16 + r    ) * 68 + col]     = acc[tn][0];
                gb[(mt * 16 + r    ) * 68 + col + 1] = acc[tn][1];
                gb[(mt * 16 + r + 8) * 68 + col]     = acc[tn][2];
                gb[(mt * 16 + r + 8) * 68 + col + 1] = acc[tn][3];
            }
        }
        __syncthreads();

        // ---- cell update: 2 rows per thread; fragment-only h output ----
        __half* hfo = (__half*)((isL2 ? g_h2f : g_h1f) + (size_t)t * FRAGBUF);
        #pragma unroll
        for (int i = 0; i < 2; i++) {
            int ri = rg * 2 + i;
            float iv = bia[0], fv = bia[1], gv = bia[2], ov = bia[3];
            #pragma unroll
            for (int g = 0; g < 4; g++) {
                const float* gb = &Gb[g * 64 * 68 + ri * 68];
                iv += gb[jb]; fv += gb[16 + jb]; gv += gb[32 + jb]; ov += gb[48 + jb];
            }
            float si = sigm(iv), sf = sigm(fv), so = sigm(ov);
            float cn = sf * cst[i] + si * tanhf(gv);
            float hn = so * tanhf(cn);
            cst[i] = cn;
            hfo[pk[i]] = __float2half_rn(hn);
        }
        __syncthreads();           // h-frag STGs ordered before release (cumulativity)
        if (tid == 0) red_release(isL2 ? &l2c[t] : &l1c[t]);
    }
}

// ---------------- fragment-direct fp16 projection GEMM ----------------------
// out[b*T + t][n] = h2(b,t) . lin_W[n] + lin_b[n]
// grid (79 n-tiles, 256 t). 8 warps = 4 m-tiles x 2 n-halves. No SMEM.
__global__ void __launch_bounds__(256, 2)
pgemm(const float* __restrict__ lin_b, float* __restrict__ out)
{
    const int tid = threadIdx.x, lane = tid & 31, wid = tid >> 5;
    const int mt = wid & 3, nh = wid >> 2;
    const int t = blockIdx.y, nb = blockIdx.x;
    const int r = lane >> 2, q = lane & 3;

    float acc[4][4];
    #pragma unroll
    for (int i = 0; i < 4; i++)
        #pragma unroll
        for (int j = 0; j < 4; j++) acc[i][j] = 0.f;

    const uint4* ab = (const uint4*)g_h2f + (size_t)t * (FRAGBUF / 4) + (mt * 64) * 32 + lane;
    const unsigned* wg = g_lwf + ((size_t)(nb * 8 + nh * 4) * 64) * 64 + lane * 2;

    #pragma unroll 8
    for (int c = 0; c < 64; c++) {
        uint4 a4 = __ldg(ab + c * 32);
        unsigned af[4] = { a4.x, a4.y, a4.z, a4.w };
        #pragma unroll
        for (int tn = 0; tn < 4; tn++) {
            const uint2 b2 = __ldg((const uint2*)(wg + ((size_t)tn * 64 + c) * 64));
            unsigned bg[2] = { b2.x, b2.y };
            mma16(acc[tn], af, bg);
        }
    }

    // epilogue: rows b = mt*16 + r, +8; out row = b*TSZ + t
    #pragma unroll
    for (int tn = 0; tn < 4; tn++) {
        int n = nb * 64 + nh * 32 + tn * 8 + 2 * q;
        if (n + 1 < VSZ) {
            float bb0 = lin_b[n], bb1 = lin_b[n + 1];
            int b0r = mt * 16 + r;
            float2 v0 = make_float2(acc[tn][0] + bb0, acc[tn][1] + bb1);
            float2 v1 = make_float2(acc[tn][2] + bb0, acc[tn][3] + bb1);
            *(float2*)&out[((size_t)b0r * TSZ + t) * VSZ + n]       = v0;
            *(float2*)&out[((size_t)(b0r + 8) * TSZ + t) * VSZ + n] = v1;
        } else if (n < VSZ) {
            float bb0 = lin_b[n];
            int b0r = mt * 16 + r;
            out[((size_t)b0r * TSZ + t) * VSZ + n]       = acc[tn][0] + bb0;
            out[((size_t)(b0r + 8) * TSZ + t) * VSZ + n] = acc[tn][2] + bb0;
        }
    }
}

// ---------------- launch ----------------------------------------------------
#define SMEM_DUAL (32768 * 4 + 4 * 64 * 68 * 4)   // 200704 bytes

extern "C" void kernel_launch(void* const* d_in, const int* in_sizes, int n_in,
                              void* d_out, int out_size)
{
    const int*   input  = (const int*)  d_in[0];
    const float* embedW = (const float*)d_in[2];
    const float* W_ih1  = (const float*)d_in[3];
    const float* W_hh1  = (const float*)d_in[4];
    const float* b_ih1  = (const float*)d_in[5];
    const float* b_hh1  = (const float*)d_in[6];
    const float* W_ih2  = (const float*)d_in[7];
    const float* W_hh2  = (const float*)d_in[8];
    const float* b_ih2  = (const float*)d_in[9];
    const float* b_hh2  = (const float*)d_in[10];
    const float* lin_W  = (const float*)d_in[11];
    const float* lin_b  = (const float*)d_in[12];
    float* out = (float*)d_out;

    cudaFuncSetAttribute(lstm_dual,
                         cudaFuncAttributeMaxDynamicSharedMemorySize, SMEM_DUAL);

    zero_ctr_kernel<<<1, 2 * TSZ>>>();
    embed_frag<<<MROWS, 128>>>(input, embedW);
    pack_wf1<<<64, 256>>>(W_ih1);
    pack_wf2<<<64, 256>>>(W_ih2);
    pack_lwf<<<NTILE, 256>>>(lin_W);

    lstm_dual<<<128, 512, SMEM_DUAL>>>(W_hh1, b_ih1, b_hh1,
                                       W_hh2, b_ih2, b_hh2);

    {   // outs = h2 @ lin_W^T + lin_b (fragment-direct fp16)
        dim3 grid(NTILE, TSZ);
        pgemm<<<grid, 256>>>(lin_b, out);
    }
}

// round 14
// speedup vs baseline: 3.1026x; 1.0532x over previous
#include <cuda_runtime.h>
#include <cuda_fp16.h>
#include <math.h>

#define VSZ 5000
#define HSZ 1024
#define ESZ 512
#define BSZ 64
#define TSZ 256
#define H4  (4 * HSZ)
#define MROWS (BSZ * TSZ)   // 16384
#define NTILE 79            // ceil(5000/64)

// ---------------- scratch ---------------------------------------------------
#define FRAGBUF (4 * 64 * 32 * 4)                     // uint32 per step-buffer
__device__ unsigned g_xf[(size_t)TSZ * FRAGBUF / 2];  // x fp16 A-frags (K=512)
__device__ unsigned g_h1f[(size_t)TSZ * FRAGBUF];     // h1 frags, all steps (32MB)
__device__ unsigned g_h2f[(size_t)TSZ * FRAGBUF];     // h2 frags, all steps (32MB)
__device__ unsigned g_wf1[64 * 8 * 32 * 64];          // W_ih1 fp16 B-frags (4MB)
__device__ unsigned g_wf2[64 * 8 * 64 * 64];          // W_ih2 fp16 B-frags (8MB)
__device__ unsigned g_lwf[(size_t)NTILE * 8 * 64 * 64];// lin_W fp16 B-frags (10.4MB)
__device__ unsigned g_ctr[2 * TSZ];

// ---------------- helpers ---------------------------------------------------
__device__ __forceinline__ unsigned pack2(float x, float y) {
    __half2 h = __floats2half2_rn(x, y);
    return *(unsigned*)&h;
}
__device__ __forceinline__ void mma16(float* c, const unsigned* a, const unsigned* b) {
    asm volatile(
        "mma.sync.aligned.m16n8k16.row.col.f32.f16.f16.f32 "
        "{%0,%1,%2,%3}, {%4,%5,%6,%7}, {%8,%9}, {%0,%1,%2,%3};\n"
        : "+f"(c[0]), "+f"(c[1]), "+f"(c[2]), "+f"(c[3])
        : "r"(a[0]), "r"(a[1]), "r"(a[2]), "r"(a[3]), "r"(b[0]), "r"(b[1]));
}
__device__ __forceinline__ void red_release(unsigned* p) {
    asm volatile("red.release.gpu.global.add.u32 [%0], 1;" :: "l"(p) : "memory");
}
__device__ __forceinline__ unsigned ld_acquire(const unsigned* p) {
    unsigned v;
    asm volatile("ld.acquire.gpu.global.b32 %0, [%1];" : "=r"(v) : "l"(p) : "memory");
    return v;
}
__device__ __forceinline__ float tanha(float x) {
    float y; asm("tanh.approx.f32 %0, %1;" : "=f"(y) : "f"(x)); return y;
}
__device__ __forceinline__ float sigm(float x) {
    return fmaf(0.5f, tanha(0.5f * x), 0.5f);
}
#define BARG1() asm volatile("bar.sync 1, 256;" ::: "memory")
#define BARG2() asm volatile("bar.sync 2, 256;" ::: "memory")

// ---------------- small kernels ----------------------------------------------
__global__ void zero_ctr_kernel() { g_ctr[threadIdx.x] = 0u; }

__global__ void embed_frag(const int* __restrict__ input,
                           const float* __restrict__ embedW)
{
    int row = blockIdx.x;            // b*TSZ + t
    int b = row >> 8, t = row & 255;
    int idx = input[row];
    int k = threadIdx.x * 4;
    float4 v = *(const float4*)(embedW + (size_t)idx * ESZ + k);
    int mt = b >> 4, ml = b & 15;
    int c = k >> 4, kk = k & 15;
    int e  = ((ml >= 8) ? 1 : 0) + ((kk >= 8) ? 2 : 0);
    int lp = (ml & 7) * 4 + ((kk & 7) >> 1);
    unsigned* base = g_xf + ((size_t)((t * 4 + mt) * 32 + c) * 32) * 4;
    base[lp * 4 + e]       = pack2(v.x, v.y);
    base[(lp + 1) * 4 + e] = pack2(v.z, v.w);
}

__global__ void pack_wf1(const float* __restrict__ Wih1)
{
    int bn = blockIdx.x, h0 = bn * 16;
    for (int idx = threadIdx.x; idx < 64 * 256; idx += 256) {
        int nl = idx >> 8, k = (idx & 255) * 2;
        int g = nl >> 4, u = nl & 15;
        float2 v = *(const float2*)&Wih1[(size_t)(g * HSZ + h0 + u) * ESZ + k];
        int c = k >> 4, kk = k & 15;
        int tn = nl >> 3, rr = nl & 7, qq = (kk & 7) >> 1, f = (kk >= 8) ? 1 : 0;
        g_wf1[((size_t)(bn * 8 + tn) * 32 + c) * 64 + (rr * 4 + qq) * 2 + f] = pack2(v.x, v.y);
    }
}

__global__ void pack_wf2(const float* __restrict__ Wih2)
{
    int bn = blockIdx.x, h0 = bn * 16;
    for (int idx = threadIdx.x; idx < 64 * 512; idx += 256) {
        int nl = idx >> 9, k = (idx & 511) * 2;
        int g = nl >> 4, u = nl & 15;
        float2 v = *(const float2*)&Wih2[(size_t)(g * HSZ + h0 + u) * HSZ + k];
        int c = k >> 4, kk = k & 15;
        int tn = nl >> 3, rr = nl & 7, qq = (kk & 7) >> 1, f = (kk >= 8) ? 1 : 0;
        g_wf2[((size_t)(bn * 8 + tn) * 64 + c) * 64 + (rr * 4 + qq) * 2 + f] = pack2(v.x, v.y);
    }
}

// lin_W (5000 x 1024) -> fp16 B-frags, rows padded with zeros to 79*64
__global__ void pack_lwf(const float* __restrict__ linW)
{
    int nb = blockIdx.x, n0 = nb * 64;
    for (int idx = threadIdx.x; idx < 64 * 512; idx += 256) {
        int nl = idx >> 9, k = (idx & 511) * 2;
        int n = n0 + nl;
        float2 v = make_float2(0.f, 0.f);
        if (n < VSZ) v = *(const float2*)&linW[(size_t)n * HSZ + k];
        int c = k >> 4, kk = k & 15;
        int tn = nl >> 3, rr = nl & 7, qq = (kk & 7) >> 1, f = (kk >= 8) ? 1 : 0;
        g_lwf[((size_t)(nb * 8 + tn) * 64 + c) * 64 + (rr * 4 + qq) * 2 + f] = pack2(v.x, v.y);
    }
}

// ---------------- dual-layer, warp-specialized persistent LSTM --------------
// 128 blocks x 512 threads. 16 warps = 2 roles x 4 m-tiles x 2 k-halves.
__global__ void __launch_bounds__(512, 1)
lstm_dual(const float* __restrict__ Whh1,
          const float* __restrict__ bi1,  const float* __restrict__ bh1,
          const float* __restrict__ Whh2,
          const float* __restrict__ bi2,  const float* __restrict__ bh2)
{
    extern __shared__ unsigned smu[];
    float* Gb = (float*)(smu + 32768);    // [4 grp][64][68]
    const int tid = threadIdx.x, lane = tid & 31, wid = tid >> 5;
    const int mt = wid & 3;
    const int kh = (wid >> 2) & 1;
    const int role = wid >> 3;
    const int grp = role * 2 + kh;
    const bool isL2 = (blockIdx.x >= 64);
    const int bn = isL2 ? (blockIdx.x - 64) : blockIdx.x;
    const int h0 = bn * 16;
    unsigned* l1c = g_ctr;
    unsigned* l2c = g_ctr + TSZ;

    // ---- load W_hh slice into SMEM fp16 B-frags (once) ----
    {
        const float* Whh = isL2 ? Whh2 : Whh1;
        for (int idx = tid; idx < 64 * 512; idx += 512) {
            int nl = idx >> 9, k = (idx & 511) * 2;
            int g = nl >> 4, u = nl & 15;
            float2 v = *(const float2*)&Whh[(size_t)(g * HSZ + h0 + u) * HSZ + k];
            int c = k >> 4, kk = k & 15;
            int tn = nl >> 3, rr = nl & 7, qq = (kk & 7) >> 1, f = (kk >= 8) ? 1 : 0;
            smu[((tn * 64 + c) * 32 + rr * 4 + qq) * 2 + f] = pack2(v.x, v.y);
        }
    }
    __syncthreads();

    // epilogue mapping: thread -> col jb, rows rg*2, rg*2+1
    const int jb = tid & 15, rg = tid >> 4;
    float bia[4];
    {
        const float* bA = isL2 ? bi2 : bi1;
        const float* bB = isL2 ? bh2 : bh1;
        #pragma unroll
        for (int g = 0; g < 4; g++)
            bia[g] = bA[g * HSZ + h0 + jb] + bB[g * HSZ + h0 + jb];
    }
    int pk[2];
    #pragma unroll
    for (int i = 0; i < 2; i++) {
        int ri = rg * 2 + i, mti = ri >> 4, ml = ri & 15;
        int lp = (ml & 7) * 4 + ((jb & 7) >> 1);
        int e  = ((ml >= 8) ? 1 : 0) + ((jb >= 8) ? 2 : 0);
        pk[i]  = (((mti * 64 + bn) * 32 + lp) * 4 + e) * 2 + (jb & 1);
    }
    float cst[2] = {0.f, 0.f};
    const int r = lane >> 2, q = lane & 3;

    for (int t = 0; t < TSZ; t++) {
        float acc[8][4];
        #pragma unroll
        for (int i = 0; i < 8; i++)
            #pragma unroll
            for (int j = 0; j < 4; j++) acc[i][j] = 0.f;

        if (!isL2) {
            if (role == 0) {
                // x-part: K=512, W from L2, no dependency
                const uint4* ax = (const uint4*)g_xf
                                  + ((size_t)(t * 4 + mt) * 32 + kh * 16) * 32 + lane;
                const unsigned* wg = g_wf1 + ((size_t)(bn * 8) * 32 + kh * 16) * 64 + lane * 2;
                #pragma unroll 8
                for (int c = 0; c < 16; c++) {
                    uint4 a4 = __ldcg(ax + c * 32);
                    unsigned af[4] = { a4.x, a4.y, a4.z, a4.w };
                    #pragma unroll
                    for (int tn = 0; tn < 8; tn++) {
                        const uint2 b2 = __ldg((const uint2*)(wg + ((size_t)tn * 32 + c) * 64));
                        unsigned bg[2] = { b2.x, b2.y };
                        mma16(acc[tn], af, bg);
                    }
                }
            } else if (t > 0) {
                if (tid == 256) { while (ld_acquire(&l1c[t - 1]) < 64) { } }
                BARG2();
                const uint4* ah = (const uint4*)g_h1f + (size_t)(t - 1) * (FRAGBUF / 4)
                                  + (mt * 64 + kh * 32) * 32 + lane;
                #pragma unroll 8
                for (int c = 0; c < 32; c++) {
                    uint4 a4 = __ldcg(ah + c * 32);
                    unsigned af[4] = { a4.x, a4.y, a4.z, a4.w };
                    #pragma unroll
                    for (int tn = 0; tn < 8; tn++) {
                        const unsigned* p = smu + (tn * 64 + kh * 32 + c) * 64 + lane * 2;
                        unsigned bg[2] = { p[0], p[1] };
                        mma16(acc[tn], af, bg);
                    }
                }
            }
        } else {
            if (role == 0) {
                if (t > 0) {
                    if (tid == 0) { while (ld_acquire(&l2c[t - 1]) < 64) { } }
                    BARG1();
                    const uint4* ah = (const uint4*)g_h2f + (size_t)(t - 1) * (FRAGBUF / 4)
                                      + (mt * 64 + kh * 32) * 32 + lane;
                    #pragma unroll 8
                    for (int c = 0; c < 32; c++) {
                        uint4 a4 = __ldcg(ah + c * 32);
                        unsigned af[4] = { a4.x, a4.y, a4.z, a4.w };
                        #pragma unroll
                        for (int tn = 0; tn < 8; tn++) {
                            const unsigned* p = smu + (tn * 64 + kh * 32 + c) * 64 + lane * 2;
                            unsigned bg[2] = { p[0], p[1] };
                            mma16(acc[tn], af, bg);
                        }
                    }
                }
            } else {
                if (tid == 256) { while (ld_acquire(&l1c[t]) < 64) { } }
                BARG2();
                const uint4* ah1 = (const uint4*)g_h1f + (size_t)t * (FRAGBUF / 4)
                                   + (mt * 64 + kh * 32) * 32 + lane;
                const unsigned* wg = g_wf2 + ((size_t)(bn * 8) * 64 + kh * 32) * 64 + lane * 2;
                #pragma unroll 8
                for (int c = 0; c < 32; c++) {
                    uint4 a4 = __ldcg(ah1 + c * 32);
                    unsigned af[4] = { a4.x, a4.y, a4.z, a4.w };
                    #pragma unroll
                    for (int tn = 0; tn < 8; tn++) {
                        const uint2 b2 = __ldg((const uint2*)(wg + ((size_t)tn * 64 + c) * 64));
                        unsigned bg[2] = { b2.x, b2.y };
                        mma16(acc[tn], af, bg);
                    }
                }
            }
        }

        // ---- stage partial sums (per group) ----
        {
            float* gb = &Gb[grp * 64 * 68];
            #pragma unroll
            for (int tn = 0; tn < 8; tn++) {
                int col = tn * 8 + 2 * q;
                gb[(mt * 16 + r    ) * 68 + col]     = acc[tn][0];
                gb[(mt * 16 + r    ) * 68 + col + 1] = acc[tn][1];
                gb[(mt * 16 + r + 8) * 68 + col]     = acc[tn][2];
                gb[(mt * 16 + r + 8) * 68 + col + 1] = acc[tn][3];
            }
        }
        __syncthreads();

        // ---- cell update: 2 rows per thread; MUFU.TANH activations ----
        __half* hfo = (__half*)((isL2 ? g_h2f : g_h1f) + (size_t)t * FRAGBUF);
        #pragma unroll
        for (int i = 0; i < 2; i++) {
            int ri = rg * 2 + i;
            float iv = bia[0], fv = bia[1], gv = bia[2], ov = bia[3];
            #pragma unroll
            for (int g = 0; g < 4; g++) {
                const float* gb = &Gb[g * 64 * 68 + ri * 68];
                iv += gb[jb]; fv += gb[16 + jb]; gv += gb[32 + jb]; ov += gb[48 + jb];
            }
            float si = sigm(iv), sf = sigm(fv), so = sigm(ov);
            float cn = sf * cst[i] + si * tanha(gv);
            float hn = so * tanha(cn);
            cst[i] = cn;
            hfo[pk[i]] = __float2half_rn(hn);
        }
        __syncthreads();           // h-frag STGs ordered before release (cumulativity)
        if (tid == 0) red_release(isL2 ? &l2c[t] : &l1c[t]);
    }
}

// ---------------- fragment-direct fp16 projection GEMM ----------------------
// out[b*T + t][n] = h2(b,t) . lin_W[n] + lin_b[n]
// grid (79 n-tiles, 128 t-pairs). 8 warps = 4 m-tiles x 2 n-halves.
// Each block handles 2 timesteps per lin_W fragment load (halves W traffic).
__global__ void __launch_bounds__(256, 2)
pgemm(const float* __restrict__ lin_b, float* __restrict__ out)
{
    const int tid = threadIdx.x, lane = tid & 31, wid = tid >> 5;
    const int mt = wid & 3, nh = wid >> 2;
    const int t0 = blockIdx.y * 2, nb = blockIdx.x;
    const int r = lane >> 2, q = lane & 3;

    float acc[2][4][4];
    #pragma unroll
    for (int s = 0; s < 2; s++)
        #pragma unroll
        for (int i = 0; i < 4; i++)
            #pragma unroll
            for (int j = 0; j < 4; j++) acc[s][i][j] = 0.f;

    const uint4* ab0 = (const uint4*)g_h2f + (size_t)t0 * (FRAGBUF / 4) + (mt * 64) * 32 + lane;
    const uint4* ab1 = ab0 + (FRAGBUF / 4);
    const unsigned* wg = g_lwf + ((size_t)(nb * 8 + nh * 4) * 64) * 64 + lane * 2;

    #pragma unroll 4
    for (int c = 0; c < 64; c++) {
        uint4 a0 = __ldg(ab0 + c * 32);
        uint4 a1 = __ldg(ab1 + c * 32);
        unsigned af0[4] = { a0.x, a0.y, a0.z, a0.w };
        unsigned af1[4] = { a1.x, a1.y, a1.z, a1.w };
        #pragma unroll
        for (int tn = 0; tn < 4; tn++) {
            const uint2 b2 = __ldg((const uint2*)(wg + ((size_t)tn * 64 + c) * 64));
            unsigned bg[2] = { b2.x, b2.y };
            mma16(acc[0][tn], af0, bg);
            mma16(acc[1][tn], af1, bg);
        }
    }

    // epilogue: rows b = mt*16 + r, +8; out row = b*TSZ + t
    #pragma unroll
    for (int s = 0; s < 2; s++) {
        int t = t0 + s;
        #pragma unroll
        for (int tn = 0; tn < 4; tn++) {
            int n = nb * 64 + nh * 32 + tn * 8 + 2 * q;
            if (n + 1 < VSZ) {
                float bb0 = lin_b[n], bb1 = lin_b[n + 1];
                int b0r = mt * 16 + r;
                float2 v0 = make_float2(acc[s][tn][0] + bb0, acc[s][tn][1] + bb1);
                float2 v1 = make_float2(acc[s][tn][2] + bb0, acc[s][tn][3] + bb1);
                *(float2*)&out[((size_t)b0r * TSZ + t) * VSZ + n]       = v0;
                *(float2*)&out[((size_t)(b0r + 8) * TSZ + t) * VSZ + n] = v1;
            } else if (n < VSZ) {
                float bb0 = lin_b[n];
                int b0r = mt * 16 + r;
                out[((size_t)b0r * TSZ + t) * VSZ + n]       = acc[s][tn][0] + bb0;
                out[((size_t)(b0r + 8) * TSZ + t) * VSZ + n] = acc[s][tn][2] + bb0;
            }
        }
    }
}

// ---------------- launch ----------------------------------------------------
#define SMEM_DUAL (32768 * 4 + 4 * 64 * 68 * 4)   // 200704 bytes

extern "C" void kernel_launch(void* const* d_in, const int* in_sizes, int n_in,
                              void* d_out, int out_size)
{
    const int*   input  = (const int*)  d_in[0];
    const float* embedW = (const float*)d_in[2];
    const float* W_ih1  = (const float*)d_in[3];
    const float* W_hh1  = (const float*)d_in[4];
    const float* b_ih1  = (const float*)d_in[5];
    const float* b_hh1  = (const float*)d_in[6];
    const float* W_ih2  = (const float*)d_in[7];
    const float* W_hh2  = (const float*)d_in[8];
    const float* b_ih2  = (const float*)d_in[9];
    const float* b_hh2  = (const float*)d_in[10];
    const float* lin_W  = (const float*)d_in[11];
    const float* lin_b  = (const float*)d_in[12];
    float* out = (float*)d_out;

    cudaFuncSetAttribute(lstm_dual,
                         cudaFuncAttributeMaxDynamicSharedMemorySize, SMEM_DUAL);

    zero_ctr_kernel<<<1, 2 * TSZ>>>();
    embed_frag<<<MROWS, 128>>>(input, embedW);
    pack_wf1<<<64, 256>>>(W_ih1);
    pack_wf2<<<64, 256>>>(W_ih2);
    pack_lwf<<<NTILE, 256>>>(lin_W);

    lstm_dual<<<128, 512, SMEM_DUAL>>>(W_hh1, b_ih1, b_hh1,
                                       W_hh2, b_ih2, b_hh2);

    {   // outs = h2 @ lin_W^T + lin_b (fragment-direct fp16, 2 t/block)
        dim3 grid(NTILE, TSZ / 2);
        pgemm<<<grid, 256>>>(lin_b, out);
    }
}